// round 1
// baseline (speedup 1.0000x reference)
#include <cuda_runtime.h>
#include <math.h>

// Problem constants
#define N_TOK 4096
#define CA 768
#define CS 384
#define CZ 128
#define NH 16
#define HD 48
#define NQW 32
#define NKW 128
#define NBW 128

// ---------------- scratch (__device__ globals; no allocation allowed) ----------------
__device__ float g_sln [N_TOK * CS];
__device__ float g_alnr[N_TOK * CA];
__device__ float g_aln [N_TOK * CA];
__device__ float g_t1  [N_TOK * CA];
__device__ float g_t2  [N_TOK * CA];
__device__ float g_q   [N_TOK * CA];
__device__ float g_k   [N_TOK * CA];
__device__ float g_v   [N_TOK * CA];
__device__ float g_g   [N_TOK * CA];
__device__ float g_o   [N_TOK * CA];
__device__ float g_bias[NH * NBW * NQW * NKW];

// ---------------- LayerNorm kernels (warp per row, exact two-pass) ----------------
__global__ __launch_bounds__(256) void ln_s_kernel(const float* __restrict__ s,
                                                   const float* __restrict__ gamma,
                                                   float* __restrict__ out)
{
    int row  = blockIdx.x * 8 + (threadIdx.x >> 5);
    int lane = threadIdx.x & 31;
    const float* x = s + (size_t)row * CS;
    float v[12];
    float sum = 0.f;
#pragma unroll
    for (int i = 0; i < 12; i++) { v[i] = x[lane + 32 * i]; sum += v[i]; }
#pragma unroll
    for (int o = 16; o; o >>= 1) sum += __shfl_xor_sync(0xffffffffu, sum, o);
    float m = sum * (1.0f / CS);
    float ss = 0.f;
#pragma unroll
    for (int i = 0; i < 12; i++) { float d = v[i] - m; ss += d * d; }
#pragma unroll
    for (int o = 16; o; o >>= 1) ss += __shfl_xor_sync(0xffffffffu, ss, o);
    float inv = rsqrtf(ss * (1.0f / CS) + 1e-5f);
    float* op = out + (size_t)row * CS;
#pragma unroll
    for (int i = 0; i < 12; i++)
        op[lane + 32 * i] = (v[i] - m) * inv * gamma[lane + 32 * i];
}

__global__ __launch_bounds__(256) void ln_a_kernel(const float* __restrict__ a,
                                                   float* __restrict__ out)
{
    int row  = blockIdx.x * 8 + (threadIdx.x >> 5);
    int lane = threadIdx.x & 31;
    const float* x = a + (size_t)row * CA;
    float v[24];
    float sum = 0.f;
#pragma unroll
    for (int i = 0; i < 24; i++) { v[i] = x[lane + 32 * i]; sum += v[i]; }
#pragma unroll
    for (int o = 16; o; o >>= 1) sum += __shfl_xor_sync(0xffffffffu, sum, o);
    float m = sum * (1.0f / CA);
    float ss = 0.f;
#pragma unroll
    for (int i = 0; i < 24; i++) { float d = v[i] - m; ss += d * d; }
#pragma unroll
    for (int o = 16; o; o >>= 1) ss += __shfl_xor_sync(0xffffffffu, ss, o);
    float inv = rsqrtf(ss * (1.0f / CA) + 1e-5f);
    float* op = out + (size_t)row * CA;
#pragma unroll
    for (int i = 0; i < 24; i++)
        op[lane + 32 * i] = (v[i] - m) * inv;
}

// ---------------- tiled fp32 GEMM: C[M,N] = A[M,K] @ B[K,N] (+bias, +sigmoid) ----------------
// BM=128, BN=64, BK=16, 256 threads, 8x4 per thread. M=4096, N=768 fixed by grid.
__global__ __launch_bounds__(256) void sgemm_k(const float* __restrict__ A,
                                               const float* __restrict__ B,
                                               const float* __restrict__ bias,
                                               float* __restrict__ C,
                                               int K, int act)
{
    const int N = 768;
    __shared__ __align__(16) float As[16][128];
    __shared__ __align__(16) float Bs[16][64];
    int tid = threadIdx.x;
    int tx = tid & 15, ty = tid >> 4;
    int row0 = blockIdx.y * 128;
    int col0 = blockIdx.x * 64;
    float acc[8][4];
#pragma unroll
    for (int i = 0; i < 8; i++)
#pragma unroll
        for (int j = 0; j < 4; j++) acc[i][j] = 0.f;

    const int ar = tid >> 1;
    const int ac = (tid & 1) * 8;
    const int br = tid >> 4;
    const int bc = (tid & 15) * 4;

    for (int k0 = 0; k0 < K; k0 += 16) {
        const float* Ap = A + (size_t)(row0 + ar) * K + k0 + ac;
        float4 a0 = *(const float4*)(Ap);
        float4 a1 = *(const float4*)(Ap + 4);
        As[ac + 0][ar] = a0.x; As[ac + 1][ar] = a0.y;
        As[ac + 2][ar] = a0.z; As[ac + 3][ar] = a0.w;
        As[ac + 4][ar] = a1.x; As[ac + 5][ar] = a1.y;
        As[ac + 6][ar] = a1.z; As[ac + 7][ar] = a1.w;
        *(float4*)&Bs[br][bc] = *(const float4*)(B + (size_t)(k0 + br) * N + col0 + bc);
        __syncthreads();
#pragma unroll
        for (int kk = 0; kk < 16; kk++) {
            float4 alo = *(const float4*)&As[kk][ty * 8];
            float4 ahi = *(const float4*)&As[kk][ty * 8 + 4];
            float4 b4  = *(const float4*)&Bs[kk][tx * 4];
            float ar_[8] = {alo.x, alo.y, alo.z, alo.w, ahi.x, ahi.y, ahi.z, ahi.w};
            float br_[4] = {b4.x, b4.y, b4.z, b4.w};
#pragma unroll
            for (int i = 0; i < 8; i++)
#pragma unroll
                for (int j = 0; j < 4; j++) acc[i][j] += ar_[i] * br_[j];
        }
        __syncthreads();
    }
#pragma unroll
    for (int i = 0; i < 8; i++) {
        int m = row0 + ty * 8 + i;
        float4 r;
        float* pr = &r.x;
#pragma unroll
        for (int j = 0; j < 4; j++) {
            float vv = acc[i][j];
            int n = col0 + tx * 4 + j;
            if (bias) vv += bias[n];
            if (act == 1) vv = 1.f / (1.f + expf(-vv));
            pr[j] = vv;
        }
        *(float4*)&C[(size_t)m * N + col0 + tx * 4] = r;
    }
}

// ---------------- bias = LN(z)*gamma @ wz ; layout [(w*16+h)][q][k] ----------------
__global__ __launch_bounds__(256) void bias_kernel(const float* __restrict__ z,
                                                   const float* __restrict__ gamma,
                                                   const float* __restrict__ wz,
                                                   float* __restrict__ bias)
{
    int warp = blockIdx.x * 8 + (threadIdx.x >> 5);  // vector index, 0..524287
    int lane = threadIdx.x & 31;
    const float* zp = z + (size_t)warp * CZ;
    float4 x = *(const float4*)(zp + lane * 4);
    float sum = x.x + x.y + x.z + x.w;
#pragma unroll
    for (int o = 16; o; o >>= 1) sum += __shfl_xor_sync(0xffffffffu, sum, o);
    float m = sum * (1.0f / CZ);
    float d0 = x.x - m, d1 = x.y - m, d2 = x.z - m, d3 = x.w - m;
    float ss = d0 * d0 + d1 * d1 + d2 * d2 + d3 * d3;
#pragma unroll
    for (int o = 16; o; o >>= 1) ss += __shfl_xor_sync(0xffffffffu, ss, o);
    float inv = rsqrtf(ss * (1.0f / CZ) + 1e-5f);
    int c0 = lane * 4;
    float l0 = d0 * inv * gamma[c0 + 0];
    float l1 = d1 * inv * gamma[c0 + 1];
    float l2 = d2 * inv * gamma[c0 + 2];
    float l3 = d3 * inv * gamma[c0 + 3];
    float part[16];
#pragma unroll
    for (int h = 0; h < 16; h++) {
        part[h] = l0 * wz[(c0 + 0) * 16 + h] + l1 * wz[(c0 + 1) * 16 + h]
                + l2 * wz[(c0 + 2) * 16 + h] + l3 * wz[(c0 + 3) * 16 + h];
    }
#pragma unroll
    for (int o = 16; o; o >>= 1)
#pragma unroll
        for (int h = 0; h < 16; h++)
            part[h] += __shfl_xor_sync(0xffffffffu, part[h], o);
    if (lane < 16) {
        int w   = warp >> 12;        // / (32*128)
        int rem = warp & 4095;       // q*128 + k
        bias[(size_t)(w * 16 + lane) * 4096 + rem] = part[lane];
    }
}

// ---------------- local attention: one CTA per (window w, head h) ----------------
// smem: qs[32*48], ks/vs[128 rows, stride 52 (float4-aligned, conflict-free)]
#define ATTN_SMEM ((32 * 48 + 2 * 128 * 52) * 4)
__global__ __launch_bounds__(256) void attn_kernel(const float* __restrict__ q,
                                                   const float* __restrict__ k,
                                                   const float* __restrict__ v,
                                                   const float* __restrict__ bias,
                                                   float* __restrict__ o)
{
    extern __shared__ float sm[];
    float* qs = sm;                 // 32*48
    float* ks = sm + 32 * 48;       // 128*52
    float* vs = ks + 128 * 52;      // 128*52
    int w = blockIdx.x, h = blockIdx.y;
    int tid = threadIdx.x;

    for (int i = tid; i < 32 * 48; i += 256) {
        int r = i / 48, c = i - r * 48;
        qs[i] = q[(size_t)(w * 32 + r) * CA + h * 48 + c];
    }
    for (int i = tid; i < 128 * 48; i += 256) {
        int r = i / 48, c = i - r * 48;
        int tok = w * 32 - 48 + r;
        tok = tok < 0 ? 0 : (tok > 4095 ? 4095 : tok);
        ks[r * 52 + c] = k[(size_t)tok * CA + h * 48 + c];
        vs[r * 52 + c] = v[(size_t)tok * CA + h * 48 + c];
    }
    __syncthreads();

    int qi = tid >> 3, g = tid & 7;
    float4 qreg[12];
#pragma unroll
    for (int j = 0; j < 12; j++) qreg[j] = *(const float4*)&qs[qi * 48 + 4 * j];

    const float scale = 0.14433756729740643f;  // 1/sqrt(48)
    float sc[16];
    const float* bp = bias + ((size_t)(w * 16 + h) * 32 + qi) * 128;
#pragma unroll
    for (int jj = 0; jj < 16; jj++) {
        int kj = g + 8 * jj;
        int tok = w * 32 - 48 + kj;
        if (tok < 0 || tok >= 4096) { sc[jj] = -1e9f; continue; }
        const float4* kp = (const float4*)&ks[kj * 52];
        float acc = 0.f;
#pragma unroll
        for (int j = 0; j < 12; j++) {
            float4 kv = kp[j];
            acc += qreg[j].x * kv.x + qreg[j].y * kv.y
                 + qreg[j].z * kv.z + qreg[j].w * kv.w;
        }
        sc[jj] = acc * scale + bp[kj];
    }
    float mx = sc[0];
#pragma unroll
    for (int jj = 1; jj < 16; jj++) mx = fmaxf(mx, sc[jj]);
#pragma unroll
    for (int o2 = 1; o2 < 8; o2 <<= 1) mx = fmaxf(mx, __shfl_xor_sync(0xffffffffu, mx, o2));
    float sum = 0.f;
#pragma unroll
    for (int jj = 0; jj < 16; jj++) { sc[jj] = expf(sc[jj] - mx); sum += sc[jj]; }
#pragma unroll
    for (int o2 = 1; o2 < 8; o2 <<= 1) sum += __shfl_xor_sync(0xffffffffu, sum, o2);
    float inv = 1.f / sum;

    float oa[48];
#pragma unroll
    for (int d = 0; d < 48; d++) oa[d] = 0.f;
#pragma unroll
    for (int jj = 0; jj < 16; jj++) {
        float p = sc[jj] * inv;
        const float4* vp = (const float4*)&vs[(g + 8 * jj) * 52];
#pragma unroll
        for (int j = 0; j < 12; j++) {
            float4 vv = vp[j];
            oa[4 * j + 0] += p * vv.x; oa[4 * j + 1] += p * vv.y;
            oa[4 * j + 2] += p * vv.z; oa[4 * j + 3] += p * vv.w;
        }
    }
#pragma unroll
    for (int o2 = 1; o2 < 8; o2 <<= 1)
#pragma unroll
        for (int d = 0; d < 48; d++)
            oa[d] += __shfl_xor_sync(0xffffffffu, oa[d], o2);
#pragma unroll
    for (int j = 0; j < 6; j++) {
        int d = g * 6 + j;
        o[(size_t)(w * 32 + qi) * CA + h * 48 + d] = oa[d];
    }
}

// ---------------- elementwise kernels ----------------
__global__ __launch_bounds__(256) void ew_aln_kernel(const float* __restrict__ t1,
                                                     const float* __restrict__ alnr,
                                                     const float* __restrict__ t2,
                                                     float* __restrict__ out)
{
    int i = blockIdx.x * 256 + threadIdx.x;
    if (i < N_TOK * CA)
        out[i] = (1.f / (1.f + expf(-t1[i]))) * alnr[i] + t2[i];
}

__global__ __launch_bounds__(256) void ew_mul_kernel(const float* __restrict__ a,
                                                     const float* __restrict__ b,
                                                     float* __restrict__ out)
{
    int i = blockIdx.x * 256 + threadIdx.x;
    if (i < N_TOK * CA) out[i] = a[i] * b[i];
}

// ---------------- launch ----------------
extern "C" void kernel_launch(void* const* d_in, const int* in_sizes, int n_in,
                              void* d_out, int out_size)
{
    const float* a        = (const float*)d_in[0];
    const float* s        = (const float*)d_in[1];
    const float* z        = (const float*)d_in[2];
    const float* gamma_s  = (const float*)d_in[3];
    const float* ws       = (const float*)d_in[4];
    const float* bs       = (const float*)d_in[5];
    const float* wskip    = (const float*)d_in[6];
    const float* lnzg     = (const float*)d_in[7];
    const float* wz       = (const float*)d_in[8];
    const float* wq       = (const float*)d_in[9];
    const float* bq       = (const float*)d_in[10];
    const float* wk       = (const float*)d_in[11];
    const float* wv       = (const float*)d_in[12];
    const float* wg       = (const float*)d_in[13];
    const float* bg       = (const float*)d_in[14];
    const float* wo       = (const float*)d_in[15];
    const float* bo       = (const float*)d_in[16];
    const float* wlast    = (const float*)d_in[17];
    const float* blast    = (const float*)d_in[18];
    float* out = (float*)d_out;

    float *p_sln, *p_alnr, *p_aln, *p_t1, *p_t2, *p_q, *p_k, *p_v, *p_g, *p_o, *p_bias;
    cudaGetSymbolAddress((void**)&p_sln,  g_sln);
    cudaGetSymbolAddress((void**)&p_alnr, g_alnr);
    cudaGetSymbolAddress((void**)&p_aln,  g_aln);
    cudaGetSymbolAddress((void**)&p_t1,   g_t1);
    cudaGetSymbolAddress((void**)&p_t2,   g_t2);
    cudaGetSymbolAddress((void**)&p_q,    g_q);
    cudaGetSymbolAddress((void**)&p_k,    g_k);
    cudaGetSymbolAddress((void**)&p_v,    g_v);
    cudaGetSymbolAddress((void**)&p_g,    g_g);
    cudaGetSymbolAddress((void**)&p_o,    g_o);
    cudaGetSymbolAddress((void**)&p_bias, g_bias);

    cudaFuncSetAttribute(attn_kernel, cudaFuncAttributeMaxDynamicSharedMemorySize, ATTN_SMEM);

    dim3 gg(12, 32);  // N tiles (768/64), M tiles (4096/128)

    ln_s_kernel<<<512, 256>>>(s, gamma_s, p_sln);
    ln_a_kernel<<<512, 256>>>(a, p_alnr);

    sgemm_k<<<gg, 256>>>(p_sln, ws,    bs,      p_t1, 384, 0);
    sgemm_k<<<gg, 256>>>(p_sln, wskip, nullptr, p_t2, 384, 0);
    ew_aln_kernel<<<12288, 256>>>(p_t1, p_alnr, p_t2, p_aln);

    sgemm_k<<<gg, 256>>>(p_aln, wq, bq,      p_q, 768, 0);
    sgemm_k<<<gg, 256>>>(p_aln, wk, nullptr, p_k, 768, 0);
    sgemm_k<<<gg, 256>>>(p_aln, wv, nullptr, p_v, 768, 0);
    sgemm_k<<<gg, 256>>>(p_aln, wg, bg,      p_g, 768, 1);

    bias_kernel<<<65536, 256>>>(z, lnzg, wz, p_bias);

    attn_kernel<<<dim3(128, 16), 256, ATTN_SMEM>>>(p_q, p_k, p_v, p_bias, p_o);

    ew_mul_kernel<<<12288, 256>>>(p_g, p_o, p_t1);
    sgemm_k<<<gg, 256>>>(p_t1, wo,    bo,    p_t2, 768, 0);
    sgemm_k<<<gg, 256>>>(s,    wlast, blast, p_t1, 384, 1);
    ew_mul_kernel<<<12288, 256>>>(p_t1, p_t2, out);
}

// round 2
// speedup vs baseline: 3.2087x; 3.2087x over previous
#include <cuda_runtime.h>
#include <math.h>

// Problem constants
#define N_TOK 4096
#define CA 768
#define CS 384
#define CZ 128
#define NH 16
#define HD 48
#define NQW 32
#define NKW 128
#define NBW 128

// ---------------- scratch (__device__ globals; no allocation allowed) ----------------
__device__ float g_sln [N_TOK * CS];
__device__ float g_alnr[N_TOK * CA];
__device__ float g_aln [N_TOK * CA];
__device__ float g_t1  [N_TOK * CA];
__device__ float g_t2  [N_TOK * CA];
__device__ float g_q   [N_TOK * CA];
__device__ float g_k   [N_TOK * CA];
__device__ float g_v   [N_TOK * CA];
__device__ float g_g   [N_TOK * CA];
__device__ float g_o   [N_TOK * CA];
__device__ float g_bias[NH * NBW * NQW * NKW];

// ---------------- LayerNorm kernels (warp per row, exact two-pass) ----------------
__global__ __launch_bounds__(256) void ln_s_kernel(const float* __restrict__ s,
                                                   const float* __restrict__ gamma,
                                                   float* __restrict__ out)
{
    int row  = blockIdx.x * 8 + (threadIdx.x >> 5);
    int lane = threadIdx.x & 31;
    const float* x = s + (size_t)row * CS;
    float v[12];
    float sum = 0.f;
#pragma unroll
    for (int i = 0; i < 12; i++) { v[i] = x[lane + 32 * i]; sum += v[i]; }
#pragma unroll
    for (int o = 16; o; o >>= 1) sum += __shfl_xor_sync(0xffffffffu, sum, o);
    float m = sum * (1.0f / CS);
    float ss = 0.f;
#pragma unroll
    for (int i = 0; i < 12; i++) { float d = v[i] - m; ss += d * d; }
#pragma unroll
    for (int o = 16; o; o >>= 1) ss += __shfl_xor_sync(0xffffffffu, ss, o);
    float inv = rsqrtf(ss * (1.0f / CS) + 1e-5f);
    float* op = out + (size_t)row * CS;
#pragma unroll
    for (int i = 0; i < 12; i++)
        op[lane + 32 * i] = (v[i] - m) * inv * gamma[lane + 32 * i];
}

__global__ __launch_bounds__(256) void ln_a_kernel(const float* __restrict__ a,
                                                   float* __restrict__ out)
{
    int row  = blockIdx.x * 8 + (threadIdx.x >> 5);
    int lane = threadIdx.x & 31;
    const float* x = a + (size_t)row * CA;
    float v[24];
    float sum = 0.f;
#pragma unroll
    for (int i = 0; i < 24; i++) { v[i] = x[lane + 32 * i]; sum += v[i]; }
#pragma unroll
    for (int o = 16; o; o >>= 1) sum += __shfl_xor_sync(0xffffffffu, sum, o);
    float m = sum * (1.0f / CA);
    float ss = 0.f;
#pragma unroll
    for (int i = 0; i < 24; i++) { float d = v[i] - m; ss += d * d; }
#pragma unroll
    for (int o = 16; o; o >>= 1) ss += __shfl_xor_sync(0xffffffffu, ss, o);
    float inv = rsqrtf(ss * (1.0f / CA) + 1e-5f);
    float* op = out + (size_t)row * CA;
#pragma unroll
    for (int i = 0; i < 24; i++)
        op[lane + 32 * i] = (v[i] - m) * inv;
}

// ---------------- tiled fp32 GEMM: C[M,N] = A[M,K] @ B[K,N] (+bias, +sigmoid) ----------------
__global__ __launch_bounds__(256) void sgemm_k(const float* __restrict__ A,
                                               const float* __restrict__ B,
                                               const float* __restrict__ bias,
                                               float* __restrict__ C,
                                               int K, int act)
{
    const int N = 768;
    __shared__ __align__(16) float As[16][128];
    __shared__ __align__(16) float Bs[16][64];
    int tid = threadIdx.x;
    int tx = tid & 15, ty = tid >> 4;
    int row0 = blockIdx.y * 128;
    int col0 = blockIdx.x * 64;
    float acc[8][4];
#pragma unroll
    for (int i = 0; i < 8; i++)
#pragma unroll
        for (int j = 0; j < 4; j++) acc[i][j] = 0.f;

    const int ar = tid >> 1;
    const int ac = (tid & 1) * 8;
    const int br = tid >> 4;
    const int bc = (tid & 15) * 4;

    for (int k0 = 0; k0 < K; k0 += 16) {
        const float* Ap = A + (size_t)(row0 + ar) * K + k0 + ac;
        float4 a0 = *(const float4*)(Ap);
        float4 a1 = *(const float4*)(Ap + 4);
        As[ac + 0][ar] = a0.x; As[ac + 1][ar] = a0.y;
        As[ac + 2][ar] = a0.z; As[ac + 3][ar] = a0.w;
        As[ac + 4][ar] = a1.x; As[ac + 5][ar] = a1.y;
        As[ac + 6][ar] = a1.z; As[ac + 7][ar] = a1.w;
        *(float4*)&Bs[br][bc] = *(const float4*)(B + (size_t)(k0 + br) * N + col0 + bc);
        __syncthreads();
#pragma unroll
        for (int kk = 0; kk < 16; kk++) {
            float4 alo = *(const float4*)&As[kk][ty * 8];
            float4 ahi = *(const float4*)&As[kk][ty * 8 + 4];
            float4 b4  = *(const float4*)&Bs[kk][tx * 4];
            float ar_[8] = {alo.x, alo.y, alo.z, alo.w, ahi.x, ahi.y, ahi.z, ahi.w};
            float br_[4] = {b4.x, b4.y, b4.z, b4.w};
#pragma unroll
            for (int i = 0; i < 8; i++)
#pragma unroll
                for (int j = 0; j < 4; j++) acc[i][j] += ar_[i] * br_[j];
        }
        __syncthreads();
    }
#pragma unroll
    for (int i = 0; i < 8; i++) {
        int m = row0 + ty * 8 + i;
        float4 r;
        float* pr = &r.x;
#pragma unroll
        for (int j = 0; j < 4; j++) {
            float vv = acc[i][j];
            int n = col0 + tx * 4 + j;
            if (bias) vv += bias[n];
            if (act == 1) vv = 1.f / (1.f + expf(-vv));
            pr[j] = vv;
        }
        *(float4*)&C[(size_t)m * N + col0 + tx * 4] = r;
    }
}

// ---------------- bias = LN(z)*gamma @ wz ; layout [(w*16+h)][q][k] ----------------
// One warp handles TWO adjacent z-vectors (one per half-warp; 8 channels/lane).
// wz staged transposed in smem: wzT[h][c] -> conflict-free LDS.128.
__global__ __launch_bounds__(256) void bias_kernel(const float* __restrict__ z,
                                                   const float* __restrict__ gamma,
                                                   const float* __restrict__ wz,
                                                   float* __restrict__ bias)
{
    __shared__ float wzs[16 * 128];   // wzT[h][c] = wz[c*16 + h]
    int tid = threadIdx.x;
    for (int idx = tid; idx < 2048; idx += 256) {
        int h = idx >> 7, c = idx & 127;
        wzs[idx] = wz[c * 16 + h];
    }
    __syncthreads();

    int warp = blockIdx.x * 8 + (tid >> 5);   // pair index, 0..262143
    int lane = tid & 31;
    int half = lane >> 4;                     // which of the 2 vectors
    int hl   = lane & 15;                     // lane within half-warp
    int vec  = warp * 2 + half;               // vector index, 0..524287

    // coalesced: warp reads 1KB contiguous (2 adjacent 512B vectors)
    const float* zp = z + (size_t)vec * CZ + hl * 8;
    float4 x0 = *(const float4*)(zp);
    float4 x1 = *(const float4*)(zp + 4);

    float sum = x0.x + x0.y + x0.z + x0.w + x1.x + x1.y + x1.z + x1.w;
#pragma unroll
    for (int o = 8; o; o >>= 1) sum += __shfl_xor_sync(0xffffffffu, sum, o);
    float m = sum * (1.0f / CZ);
    float d[8] = {x0.x - m, x0.y - m, x0.z - m, x0.w - m,
                  x1.x - m, x1.y - m, x1.z - m, x1.w - m};
    float ss = 0.f;
#pragma unroll
    for (int j = 0; j < 8; j++) ss += d[j] * d[j];
#pragma unroll
    for (int o = 8; o; o >>= 1) ss += __shfl_xor_sync(0xffffffffu, ss, o);
    float inv = rsqrtf(ss * (1.0f / CZ) + 1e-5f);

    int c0 = hl * 8;
    float4 g0 = *(const float4*)(gamma + c0);
    float4 g1 = *(const float4*)(gamma + c0 + 4);
    float l[8];
    l[0] = d[0] * inv * g0.x; l[1] = d[1] * inv * g0.y;
    l[2] = d[2] * inv * g0.z; l[3] = d[3] * inv * g0.w;
    l[4] = d[4] * inv * g1.x; l[5] = d[5] * inv * g1.y;
    l[6] = d[6] * inv * g1.z; l[7] = d[7] * inv * g1.w;

    float part[16];
#pragma unroll
    for (int h = 0; h < 16; h++) {
        const float4* wp = (const float4*)&wzs[h * 128 + c0];
        float4 w0 = wp[0], w1 = wp[1];
        part[h] = l[0] * w0.x + l[1] * w0.y + l[2] * w0.z + l[3] * w0.w
                + l[4] * w1.x + l[5] * w1.y + l[6] * w1.z + l[7] * w1.w;
    }
    // reduce across each half-warp (xor 1,2,4,8 stays within the 16-lane group)
#pragma unroll
    for (int o = 8; o; o >>= 1)
#pragma unroll
        for (int h = 0; h < 16; h++)
            part[h] += __shfl_xor_sync(0xffffffffu, part[h], o);

    // lane writes its own head h = hl
    int w   = vec >> 12;       // / (32*128)
    int rem = vec & 4095;      // q*128 + k
    bias[(size_t)(w * 16 + hl) * 4096 + rem] = part[hl];
}

// ---------------- local attention: one CTA per (window w, head h) ----------------
#define ATTN_SMEM ((32 * 48 + 2 * 128 * 52) * 4)
__global__ __launch_bounds__(256) void attn_kernel(const float* __restrict__ q,
                                                   const float* __restrict__ k,
                                                   const float* __restrict__ v,
                                                   const float* __restrict__ bias,
                                                   float* __restrict__ o)
{
    extern __shared__ float sm[];
    float* qs = sm;                 // 32*48
    float* ks = sm + 32 * 48;       // 128*52
    float* vs = ks + 128 * 52;      // 128*52
    int w = blockIdx.x, h = blockIdx.y;
    int tid = threadIdx.x;

    for (int i = tid; i < 32 * 48; i += 256) {
        int r = i / 48, c = i - r * 48;
        qs[i] = q[(size_t)(w * 32 + r) * CA + h * 48 + c];
    }
    for (int i = tid; i < 128 * 48; i += 256) {
        int r = i / 48, c = i - r * 48;
        int tok = w * 32 - 48 + r;
        tok = tok < 0 ? 0 : (tok > 4095 ? 4095 : tok);
        ks[r * 52 + c] = k[(size_t)tok * CA + h * 48 + c];
        vs[r * 52 + c] = v[(size_t)tok * CA + h * 48 + c];
    }
    __syncthreads();

    int qi = tid >> 3, g = tid & 7;
    float4 qreg[12];
#pragma unroll
    for (int j = 0; j < 12; j++) qreg[j] = *(const float4*)&qs[qi * 48 + 4 * j];

    const float scale = 0.14433756729740643f;  // 1/sqrt(48)
    float sc[16];
    const float* bp = bias + ((size_t)(w * 16 + h) * 32 + qi) * 128;
#pragma unroll
    for (int jj = 0; jj < 16; jj++) {
        int kj = g + 8 * jj;
        int tok = w * 32 - 48 + kj;
        if (tok < 0 || tok >= 4096) { sc[jj] = -1e9f; continue; }
        const float4* kp = (const float4*)&ks[kj * 52];
        float acc = 0.f;
#pragma unroll
        for (int j = 0; j < 12; j++) {
            float4 kv = kp[j];
            acc += qreg[j].x * kv.x + qreg[j].y * kv.y
                 + qreg[j].z * kv.z + qreg[j].w * kv.w;
        }
        sc[jj] = acc * scale + bp[kj];
    }
    float mx = sc[0];
#pragma unroll
    for (int jj = 1; jj < 16; jj++) mx = fmaxf(mx, sc[jj]);
#pragma unroll
    for (int o2 = 1; o2 < 8; o2 <<= 1) mx = fmaxf(mx, __shfl_xor_sync(0xffffffffu, mx, o2));
    float sum = 0.f;
#pragma unroll
    for (int jj = 0; jj < 16; jj++) { sc[jj] = expf(sc[jj] - mx); sum += sc[jj]; }
#pragma unroll
    for (int o2 = 1; o2 < 8; o2 <<= 1) sum += __shfl_xor_sync(0xffffffffu, sum, o2);
    float inv = 1.f / sum;

    float oa[48];
#pragma unroll
    for (int d = 0; d < 48; d++) oa[d] = 0.f;
#pragma unroll
    for (int jj = 0; jj < 16; jj++) {
        float p = sc[jj] * inv;
        const float4* vp = (const float4*)&vs[(g + 8 * jj) * 52];
#pragma unroll
        for (int j = 0; j < 12; j++) {
            float4 vv = vp[j];
            oa[4 * j + 0] += p * vv.x; oa[4 * j + 1] += p * vv.y;
            oa[4 * j + 2] += p * vv.z; oa[4 * j + 3] += p * vv.w;
        }
    }
#pragma unroll
    for (int o2 = 1; o2 < 8; o2 <<= 1)
#pragma unroll
        for (int d = 0; d < 48; d++)
            oa[d] += __shfl_xor_sync(0xffffffffu, oa[d], o2);
#pragma unroll
    for (int j = 0; j < 6; j++) {
        int d = g * 6 + j;
        o[(size_t)(w * 32 + qi) * CA + h * 48 + d] = oa[d];
    }
}

// ---------------- elementwise kernels ----------------
__global__ __launch_bounds__(256) void ew_aln_kernel(const float* __restrict__ t1,
                                                     const float* __restrict__ alnr,
                                                     const float* __restrict__ t2,
                                                     float* __restrict__ out)
{
    int i = blockIdx.x * 256 + threadIdx.x;
    if (i < N_TOK * CA)
        out[i] = (1.f / (1.f + expf(-t1[i]))) * alnr[i] + t2[i];
}

__global__ __launch_bounds__(256) void ew_mul_kernel(const float* __restrict__ a,
                                                     const float* __restrict__ b,
                                                     float* __restrict__ out)
{
    int i = blockIdx.x * 256 + threadIdx.x;
    if (i < N_TOK * CA) out[i] = a[i] * b[i];
}

// ---------------- launch ----------------
extern "C" void kernel_launch(void* const* d_in, const int* in_sizes, int n_in,
                              void* d_out, int out_size)
{
    const float* a        = (const float*)d_in[0];
    const float* s        = (const float*)d_in[1];
    const float* z        = (const float*)d_in[2];
    const float* gamma_s  = (const float*)d_in[3];
    const float* ws       = (const float*)d_in[4];
    const float* bs       = (const float*)d_in[5];
    const float* wskip    = (const float*)d_in[6];
    const float* lnzg     = (const float*)d_in[7];
    const float* wz       = (const float*)d_in[8];
    const float* wq       = (const float*)d_in[9];
    const float* bq       = (const float*)d_in[10];
    const float* wk       = (const float*)d_in[11];
    const float* wv       = (const float*)d_in[12];
    const float* wg       = (const float*)d_in[13];
    const float* bg       = (const float*)d_in[14];
    const float* wo       = (const float*)d_in[15];
    const float* bo       = (const float*)d_in[16];
    const float* wlast    = (const float*)d_in[17];
    const float* blast    = (const float*)d_in[18];
    float* out = (float*)d_out;

    float *p_sln, *p_alnr, *p_aln, *p_t1, *p_t2, *p_q, *p_k, *p_v, *p_g, *p_o, *p_bias;
    cudaGetSymbolAddress((void**)&p_sln,  g_sln);
    cudaGetSymbolAddress((void**)&p_alnr, g_alnr);
    cudaGetSymbolAddress((void**)&p_aln,  g_aln);
    cudaGetSymbolAddress((void**)&p_t1,   g_t1);
    cudaGetSymbolAddress((void**)&p_t2,   g_t2);
    cudaGetSymbolAddress((void**)&p_q,    g_q);
    cudaGetSymbolAddress((void**)&p_k,    g_k);
    cudaGetSymbolAddress((void**)&p_v,    g_v);
    cudaGetSymbolAddress((void**)&p_g,    g_g);
    cudaGetSymbolAddress((void**)&p_o,    g_o);
    cudaGetSymbolAddress((void**)&p_bias, g_bias);

    cudaFuncSetAttribute(attn_kernel, cudaFuncAttributeMaxDynamicSharedMemorySize, ATTN_SMEM);

    dim3 gg(12, 32);  // N tiles (768/64), M tiles (4096/128)

    ln_s_kernel<<<512, 256>>>(s, gamma_s, p_sln);
    ln_a_kernel<<<512, 256>>>(a, p_alnr);

    sgemm_k<<<gg, 256>>>(p_sln, ws,    bs,      p_t1, 384, 0);
    sgemm_k<<<gg, 256>>>(p_sln, wskip, nullptr, p_t2, 384, 0);
    ew_aln_kernel<<<12288, 256>>>(p_t1, p_alnr, p_t2, p_aln);

    sgemm_k<<<gg, 256>>>(p_aln, wq, bq,      p_q, 768, 0);
    sgemm_k<<<gg, 256>>>(p_aln, wk, nullptr, p_k, 768, 0);
    sgemm_k<<<gg, 256>>>(p_aln, wv, nullptr, p_v, 768, 0);
    sgemm_k<<<gg, 256>>>(p_aln, wg, bg,      p_g, 768, 1);

    // 524288 vectors, 2 per warp, 16 per block -> 32768 blocks
    bias_kernel<<<32768, 256>>>(z, lnzg, wz, p_bias);

    attn_kernel<<<dim3(128, 16), 256, ATTN_SMEM>>>(p_q, p_k, p_v, p_bias, p_o);

    ew_mul_kernel<<<12288, 256>>>(p_g, p_o, p_t1);
    sgemm_k<<<gg, 256>>>(p_t1, wo,    bo,    p_t2, 768, 0);
    sgemm_k<<<gg, 256>>>(s,    wlast, blast, p_t1, 384, 1);
    ew_mul_kernel<<<12288, 256>>>(p_t1, p_t2, out);
}

// round 3
// speedup vs baseline: 4.3050x; 1.3417x over previous
#include <cuda_runtime.h>
#include <math.h>
#include <stdint.h>

// Problem constants
#define N_TOK 4096
#define CA 768
#define CS 384
#define CZ 128
#define NH 16
#define HD 48
#define NQW 32
#define NKW 128
#define NBW 128

// ---------------- scratch ----------------
__device__ float g_sln [N_TOK * CS];
__device__ float g_alnr[N_TOK * CA];
__device__ float g_aln [N_TOK * CA];
__device__ float g_t1  [N_TOK * CA];
__device__ float g_t2  [N_TOK * CA];
__device__ float g_q   [N_TOK * CA];
__device__ float g_k   [N_TOK * CA];
__device__ float g_v   [N_TOK * CA];
__device__ float g_g   [N_TOK * CA];
__device__ float g_o   [N_TOK * CA];
__device__ float g_bias[NH * NBW * NQW * NKW];

// ---------------- LayerNorm kernels ----------------
__global__ __launch_bounds__(256) void ln_s_kernel(const float* __restrict__ s,
                                                   const float* __restrict__ gamma,
                                                   float* __restrict__ out)
{
    int row  = blockIdx.x * 8 + (threadIdx.x >> 5);
    int lane = threadIdx.x & 31;
    const float* x = s + (size_t)row * CS;
    float v[12];
    float sum = 0.f;
#pragma unroll
    for (int i = 0; i < 12; i++) { v[i] = x[lane + 32 * i]; sum += v[i]; }
#pragma unroll
    for (int o = 16; o; o >>= 1) sum += __shfl_xor_sync(0xffffffffu, sum, o);
    float m = sum * (1.0f / CS);
    float ss = 0.f;
#pragma unroll
    for (int i = 0; i < 12; i++) { float d = v[i] - m; ss += d * d; }
#pragma unroll
    for (int o = 16; o; o >>= 1) ss += __shfl_xor_sync(0xffffffffu, ss, o);
    float inv = rsqrtf(ss * (1.0f / CS) + 1e-5f);
    float* op = out + (size_t)row * CS;
#pragma unroll
    for (int i = 0; i < 12; i++)
        op[lane + 32 * i] = (v[i] - m) * inv * gamma[lane + 32 * i];
}

__global__ __launch_bounds__(256) void ln_a_kernel(const float* __restrict__ a,
                                                   float* __restrict__ out)
{
    int row  = blockIdx.x * 8 + (threadIdx.x >> 5);
    int lane = threadIdx.x & 31;
    const float* x = a + (size_t)row * CA;
    float v[24];
    float sum = 0.f;
#pragma unroll
    for (int i = 0; i < 24; i++) { v[i] = x[lane + 32 * i]; sum += v[i]; }
#pragma unroll
    for (int o = 16; o; o >>= 1) sum += __shfl_xor_sync(0xffffffffu, sum, o);
    float m = sum * (1.0f / CA);
    float ss = 0.f;
#pragma unroll
    for (int i = 0; i < 24; i++) { float d = v[i] - m; ss += d * d; }
#pragma unroll
    for (int o = 16; o; o >>= 1) ss += __shfl_xor_sync(0xffffffffu, ss, o);
    float inv = rsqrtf(ss * (1.0f / CA) + 1e-5f);
    float* op = out + (size_t)row * CA;
#pragma unroll
    for (int i = 0; i < 24; i++)
        op[lane + 32 * i] = (v[i] - m) * inv;
}

// ---------------- TF32 tensor-core GEMM ----------------
// C[M,768] = act(A[M,K] (* A2) @ B[K,768] + bias) (* emul)
// BM=128, BN=64, BK=16; 8 warps (4x2); warp tile 32x32 = 2x4 m16n8k8.
__device__ __forceinline__ uint32_t f2tf(float x)
{
    uint32_t r;
    asm("cvt.rna.tf32.f32 %0, %1;" : "=r"(r) : "f"(x));
    return r;
}

__device__ __forceinline__ void mma8(float* c, const uint32_t* a, const uint32_t* b)
{
    asm volatile("mma.sync.aligned.m16n8k8.row.col.f32.tf32.tf32.f32 "
                 "{%0,%1,%2,%3}, {%4,%5,%6,%7}, {%8,%9}, {%0,%1,%2,%3};"
                 : "+f"(c[0]), "+f"(c[1]), "+f"(c[2]), "+f"(c[3])
                 : "r"(a[0]), "r"(a[1]), "r"(a[2]), "r"(a[3]),
                   "r"(b[0]), "r"(b[1]));
}

#define AS_STRIDE 136   // 128 + 8 pad: banks (8k+m)%32 conflict-free frag loads
#define BS_STRIDE 72    // 64 + 8 pad

__global__ __launch_bounds__(256) void tgemm_k(const float* __restrict__ A,
                                               const float* __restrict__ A2,   // optional: A_eff = A*A2
                                               const float* __restrict__ B,
                                               const float* __restrict__ bias, // optional
                                               const float* __restrict__ emul, // optional: C *= emul
                                               float* __restrict__ C,
                                               int K, int act)
{
    __shared__ uint32_t As[16 * AS_STRIDE];
    __shared__ uint32_t Bs[16 * BS_STRIDE];

    int tid = threadIdx.x;
    int wid = tid >> 5, lane = tid & 31;
    int warp_m = wid >> 1, warp_n = wid & 1;
    int group = lane >> 2, tg = lane & 3;
    int row0 = blockIdx.y * 128;
    int col0 = blockIdx.x * 64;

    // staging assignment
    int arow = tid >> 1, akp = (tid & 1) * 8;    // A: 128 rows x 16 k, 8 floats/thread
    int brow = tid >> 4, bcol = (tid & 15) * 4;  // B: 16 rows x 64 cols, 4 floats/thread

    const float* Abase  = A  + (size_t)(row0 + arow) * K;
    const float* A2base = A2 ? A2 + (size_t)(row0 + arow) * K : nullptr;

    float acc[2][4][4];
#pragma unroll
    for (int mt = 0; mt < 2; mt++)
#pragma unroll
        for (int nt = 0; nt < 4; nt++)
#pragma unroll
            for (int r = 0; r < 4; r++) acc[mt][nt][r] = 0.f;

    // stage tile 0
    {
        float4 va0 = *(const float4*)(Abase + akp);
        float4 va1 = *(const float4*)(Abase + akp + 4);
        if (A2base) {
            float4 w0 = *(const float4*)(A2base + akp);
            float4 w1 = *(const float4*)(A2base + akp + 4);
            va0.x *= w0.x; va0.y *= w0.y; va0.z *= w0.z; va0.w *= w0.w;
            va1.x *= w1.x; va1.y *= w1.y; va1.z *= w1.z; va1.w *= w1.w;
        }
        float4 vb = *(const float4*)(B + (size_t)brow * 768 + col0 + bcol);
        float av[8] = {va0.x, va0.y, va0.z, va0.w, va1.x, va1.y, va1.z, va1.w};
#pragma unroll
        for (int i = 0; i < 8; i++) As[(akp + i) * AS_STRIDE + arow] = f2tf(av[i]);
        float bv[4] = {vb.x, vb.y, vb.z, vb.w};
#pragma unroll
        for (int i = 0; i < 4; i++) Bs[brow * BS_STRIDE + bcol + i] = f2tf(bv[i]);
    }

    for (int k0 = 0; k0 < K; k0 += 16) {
        __syncthreads();
        bool has_next = (k0 + 16) < K;
        float4 va0, va1, vb;
        if (has_next) {
            va0 = *(const float4*)(Abase + k0 + 16 + akp);
            va1 = *(const float4*)(Abase + k0 + 16 + akp + 4);
            if (A2base) {
                float4 w0 = *(const float4*)(A2base + k0 + 16 + akp);
                float4 w1 = *(const float4*)(A2base + k0 + 16 + akp + 4);
                va0.x *= w0.x; va0.y *= w0.y; va0.z *= w0.z; va0.w *= w0.w;
                va1.x *= w1.x; va1.y *= w1.y; va1.z *= w1.z; va1.w *= w1.w;
            }
            vb = *(const float4*)(B + (size_t)(k0 + 16 + brow) * 768 + col0 + bcol);
        }

        // compute: 2 k8 steps
#pragma unroll
        for (int kc = 0; kc < 2; kc++) {
            int kb = kc * 8;
            uint32_t afr[2][4];
#pragma unroll
            for (int mt = 0; mt < 2; mt++) {
                int m = warp_m * 32 + mt * 16 + group;
                afr[mt][0] = As[(kb + tg) * AS_STRIDE + m];
                afr[mt][1] = As[(kb + tg) * AS_STRIDE + m + 8];
                afr[mt][2] = As[(kb + tg + 4) * AS_STRIDE + m];
                afr[mt][3] = As[(kb + tg + 4) * AS_STRIDE + m + 8];
            }
            uint32_t bfr[4][2];
#pragma unroll
            for (int nt = 0; nt < 4; nt++) {
                int n = warp_n * 32 + nt * 8 + group;
                bfr[nt][0] = Bs[(kb + tg) * BS_STRIDE + n];
                bfr[nt][1] = Bs[(kb + tg + 4) * BS_STRIDE + n];
            }
#pragma unroll
            for (int mt = 0; mt < 2; mt++)
#pragma unroll
                for (int nt = 0; nt < 4; nt++)
                    mma8(acc[mt][nt], afr[mt], bfr[nt]);
        }

        __syncthreads();
        if (has_next) {
            float av[8] = {va0.x, va0.y, va0.z, va0.w, va1.x, va1.y, va1.z, va1.w};
#pragma unroll
            for (int i = 0; i < 8; i++) As[(akp + i) * AS_STRIDE + arow] = f2tf(av[i]);
            float bv[4] = {vb.x, vb.y, vb.z, vb.w};
#pragma unroll
            for (int i = 0; i < 4; i++) Bs[brow * BS_STRIDE + bcol + i] = f2tf(bv[i]);
        }
    }

    // epilogue
#pragma unroll
    for (int mt = 0; mt < 2; mt++) {
#pragma unroll
        for (int nt = 0; nt < 4; nt++) {
            int col = col0 + warp_n * 32 + nt * 8 + tg * 2;
            float b0 = bias ? bias[col]     : 0.f;
            float b1 = bias ? bias[col + 1] : 0.f;
#pragma unroll
            for (int half = 0; half < 2; half++) {
                int row = row0 + warp_m * 32 + mt * 16 + group + half * 8;
                float v0 = acc[mt][nt][half * 2 + 0] + b0;
                float v1 = acc[mt][nt][half * 2 + 1] + b1;
                if (act == 1) {
                    v0 = 1.f / (1.f + expf(-v0));
                    v1 = 1.f / (1.f + expf(-v1));
                }
                if (emul) {
                    v0 *= emul[(size_t)row * 768 + col];
                    v1 *= emul[(size_t)row * 768 + col + 1];
                }
                float2 r = make_float2(v0, v1);
                *(float2*)&C[(size_t)row * 768 + col] = r;
            }
        }
    }
}

// ---------------- bias = LN(z)*gamma @ wz ----------------
__global__ __launch_bounds__(256) void bias_kernel(const float* __restrict__ z,
                                                   const float* __restrict__ gamma,
                                                   const float* __restrict__ wz,
                                                   float* __restrict__ bias)
{
    __shared__ float wzs[16 * 128];   // wzT[h][c]
    int tid = threadIdx.x;
    for (int idx = tid; idx < 2048; idx += 256) {
        int h = idx >> 7, c = idx & 127;
        wzs[idx] = wz[c * 16 + h];
    }
    __syncthreads();

    int warp = blockIdx.x * 8 + (tid >> 5);
    int lane = tid & 31;
    int half = lane >> 4;
    int hl   = lane & 15;
    int vec  = warp * 2 + half;

    const float* zp = z + (size_t)vec * CZ + hl * 8;
    float4 x0 = *(const float4*)(zp);
    float4 x1 = *(const float4*)(zp + 4);

    float sum = x0.x + x0.y + x0.z + x0.w + x1.x + x1.y + x1.z + x1.w;
#pragma unroll
    for (int o = 8; o; o >>= 1) sum += __shfl_xor_sync(0xffffffffu, sum, o);
    float m = sum * (1.0f / CZ);
    float d[8] = {x0.x - m, x0.y - m, x0.z - m, x0.w - m,
                  x1.x - m, x1.y - m, x1.z - m, x1.w - m};
    float ss = 0.f;
#pragma unroll
    for (int j = 0; j < 8; j++) ss += d[j] * d[j];
#pragma unroll
    for (int o = 8; o; o >>= 1) ss += __shfl_xor_sync(0xffffffffu, ss, o);
    float inv = rsqrtf(ss * (1.0f / CZ) + 1e-5f);

    int c0 = hl * 8;
    float4 g0 = *(const float4*)(gamma + c0);
    float4 g1 = *(const float4*)(gamma + c0 + 4);
    float l[8];
    l[0] = d[0] * inv * g0.x; l[1] = d[1] * inv * g0.y;
    l[2] = d[2] * inv * g0.z; l[3] = d[3] * inv * g0.w;
    l[4] = d[4] * inv * g1.x; l[5] = d[5] * inv * g1.y;
    l[6] = d[6] * inv * g1.z; l[7] = d[7] * inv * g1.w;

    float part[16];
#pragma unroll
    for (int h = 0; h < 16; h++) {
        const float4* wp = (const float4*)&wzs[h * 128 + c0];
        float4 w0 = wp[0], w1 = wp[1];
        part[h] = l[0] * w0.x + l[1] * w0.y + l[2] * w0.z + l[3] * w0.w
                + l[4] * w1.x + l[5] * w1.y + l[6] * w1.z + l[7] * w1.w;
    }
#pragma unroll
    for (int o = 8; o; o >>= 1)
#pragma unroll
        for (int h = 0; h < 16; h++)
            part[h] += __shfl_xor_sync(0xffffffffu, part[h], o);

    int w   = vec >> 12;
    int rem = vec & 4095;
    bias[(size_t)(w * 16 + hl) * 4096 + rem] = part[hl];
}

// ---------------- local attention ----------------
#define ATTN_SMEM ((32 * 48 + 2 * 128 * 52) * 4)
__global__ __launch_bounds__(256) void attn_kernel(const float* __restrict__ q,
                                                   const float* __restrict__ k,
                                                   const float* __restrict__ v,
                                                   const float* __restrict__ bias,
                                                   float* __restrict__ o)
{
    extern __shared__ float sm[];
    float* qs = sm;
    float* ks = sm + 32 * 48;
    float* vs = ks + 128 * 52;
    int w = blockIdx.x, h = blockIdx.y;
    int tid = threadIdx.x;

    for (int i = tid; i < 32 * 48; i += 256) {
        int r = i / 48, c = i - r * 48;
        qs[i] = q[(size_t)(w * 32 + r) * CA + h * 48 + c];
    }
    for (int i = tid; i < 128 * 48; i += 256) {
        int r = i / 48, c = i - r * 48;
        int tok = w * 32 - 48 + r;
        tok = tok < 0 ? 0 : (tok > 4095 ? 4095 : tok);
        ks[r * 52 + c] = k[(size_t)tok * CA + h * 48 + c];
        vs[r * 52 + c] = v[(size_t)tok * CA + h * 48 + c];
    }
    __syncthreads();

    int qi = tid >> 3, g = tid & 7;
    float4 qreg[12];
#pragma unroll
    for (int j = 0; j < 12; j++) qreg[j] = *(const float4*)&qs[qi * 48 + 4 * j];

    const float scale = 0.14433756729740643f;
    float sc[16];
    const float* bp = bias + ((size_t)(w * 16 + h) * 32 + qi) * 128;
#pragma unroll
    for (int jj = 0; jj < 16; jj++) {
        int kj = g + 8 * jj;
        int tok = w * 32 - 48 + kj;
        if (tok < 0 || tok >= 4096) { sc[jj] = -1e9f; continue; }
        const float4* kp = (const float4*)&ks[kj * 52];
        float acc = 0.f;
#pragma unroll
        for (int j = 0; j < 12; j++) {
            float4 kv = kp[j];
            acc += qreg[j].x * kv.x + qreg[j].y * kv.y
                 + qreg[j].z * kv.z + qreg[j].w * kv.w;
        }
        sc[jj] = acc * scale + bp[kj];
    }
    float mx = sc[0];
#pragma unroll
    for (int jj = 1; jj < 16; jj++) mx = fmaxf(mx, sc[jj]);
#pragma unroll
    for (int o2 = 1; o2 < 8; o2 <<= 1) mx = fmaxf(mx, __shfl_xor_sync(0xffffffffu, mx, o2));
    float sum = 0.f;
#pragma unroll
    for (int jj = 0; jj < 16; jj++) { sc[jj] = expf(sc[jj] - mx); sum += sc[jj]; }
#pragma unroll
    for (int o2 = 1; o2 < 8; o2 <<= 1) sum += __shfl_xor_sync(0xffffffffu, sum, o2);
    float inv = 1.f / sum;

    float oa[48];
#pragma unroll
    for (int d = 0; d < 48; d++) oa[d] = 0.f;
#pragma unroll
    for (int jj = 0; jj < 16; jj++) {
        float p = sc[jj] * inv;
        const float4* vp = (const float4*)&vs[(g + 8 * jj) * 52];
#pragma unroll
        for (int j = 0; j < 12; j++) {
            float4 vv = vp[j];
            oa[4 * j + 0] += p * vv.x; oa[4 * j + 1] += p * vv.y;
            oa[4 * j + 2] += p * vv.z; oa[4 * j + 3] += p * vv.w;
        }
    }
#pragma unroll
    for (int o2 = 1; o2 < 8; o2 <<= 1)
#pragma unroll
        for (int d = 0; d < 48; d++)
            oa[d] += __shfl_xor_sync(0xffffffffu, oa[d], o2);
#pragma unroll
    for (int j = 0; j < 6; j++) {
        int d = g * 6 + j;
        o[(size_t)(w * 32 + qi) * CA + h * 48 + d] = oa[d];
    }
}

// ---------------- elementwise ----------------
__global__ __launch_bounds__(256) void ew_aln_kernel(const float* __restrict__ t1,
                                                     const float* __restrict__ alnr,
                                                     const float* __restrict__ t2,
                                                     float* __restrict__ out)
{
    int i = blockIdx.x * 256 + threadIdx.x;
    if (i < N_TOK * CA)
        out[i] = (1.f / (1.f + expf(-t1[i]))) * alnr[i] + t2[i];
}

// ---------------- launch ----------------
extern "C" void kernel_launch(void* const* d_in, const int* in_sizes, int n_in,
                              void* d_out, int out_size)
{
    const float* a        = (const float*)d_in[0];
    const float* s        = (const float*)d_in[1];
    const float* z        = (const float*)d_in[2];
    const float* gamma_s  = (const float*)d_in[3];
    const float* ws       = (const float*)d_in[4];
    const float* bs       = (const float*)d_in[5];
    const float* wskip    = (const float*)d_in[6];
    const float* lnzg     = (const float*)d_in[7];
    const float* wz       = (const float*)d_in[8];
    const float* wq       = (const float*)d_in[9];
    const float* bq       = (const float*)d_in[10];
    const float* wk       = (const float*)d_in[11];
    const float* wv       = (const float*)d_in[12];
    const float* wg       = (const float*)d_in[13];
    const float* bg       = (const float*)d_in[14];
    const float* wo       = (const float*)d_in[15];
    const float* bo       = (const float*)d_in[16];
    const float* wlast    = (const float*)d_in[17];
    const float* blast    = (const float*)d_in[18];
    float* out = (float*)d_out;

    float *p_sln, *p_alnr, *p_aln, *p_t1, *p_t2, *p_q, *p_k, *p_v, *p_g, *p_o, *p_bias;
    cudaGetSymbolAddress((void**)&p_sln,  g_sln);
    cudaGetSymbolAddress((void**)&p_alnr, g_alnr);
    cudaGetSymbolAddress((void**)&p_aln,  g_aln);
    cudaGetSymbolAddress((void**)&p_t1,   g_t1);
    cudaGetSymbolAddress((void**)&p_t2,   g_t2);
    cudaGetSymbolAddress((void**)&p_q,    g_q);
    cudaGetSymbolAddress((void**)&p_k,    g_k);
    cudaGetSymbolAddress((void**)&p_v,    g_v);
    cudaGetSymbolAddress((void**)&p_g,    g_g);
    cudaGetSymbolAddress((void**)&p_o,    g_o);
    cudaGetSymbolAddress((void**)&p_bias, g_bias);

    cudaFuncSetAttribute(attn_kernel, cudaFuncAttributeMaxDynamicSharedMemorySize, ATTN_SMEM);

    dim3 gg(12, 32);

    ln_s_kernel<<<512, 256>>>(s, gamma_s, p_sln);
    ln_a_kernel<<<512, 256>>>(a, p_alnr);

    tgemm_k<<<gg, 256>>>(p_sln, nullptr, ws,    bs,      nullptr, p_t1, 384, 0);
    tgemm_k<<<gg, 256>>>(p_sln, nullptr, wskip, nullptr, nullptr, p_t2, 384, 0);
    ew_aln_kernel<<<12288, 256>>>(p_t1, p_alnr, p_t2, p_aln);

    tgemm_k<<<gg, 256>>>(p_aln, nullptr, wq, bq,      nullptr, p_q, 768, 0);
    tgemm_k<<<gg, 256>>>(p_aln, nullptr, wk, nullptr, nullptr, p_k, 768, 0);
    tgemm_k<<<gg, 256>>>(p_aln, nullptr, wv, nullptr, nullptr, p_v, 768, 0);
    tgemm_k<<<gg, 256>>>(p_aln, nullptr, wg, bg,      nullptr, p_g, 768, 1);

    bias_kernel<<<32768, 256>>>(z, lnzg, wz, p_bias);

    attn_kernel<<<dim3(128, 16), 256, ATTN_SMEM>>>(p_q, p_k, p_v, p_bias, p_o);

    // t2 = (g * o) @ wo + bo   (elementwise mul fused into A-staging)
    tgemm_k<<<gg, 256>>>(p_o, p_g, wo, bo, nullptr, p_t2, 768, 0);
    // out = sigmoid(s @ wlast + blast) * t2   (final mul fused into epilogue)
    tgemm_k<<<gg, 256>>>(s, nullptr, wlast, blast, p_t2, out, 384, 1);
}

// round 4
// speedup vs baseline: 6.3414x; 1.4730x over previous
#include <cuda_runtime.h>
#include <math.h>
#include <stdint.h>

// Problem constants
#define N_TOK 4096
#define CA 768
#define CS 384
#define CZ 128
#define NH 16
#define HD 48
#define NQW 32
#define NKW 128
#define NBW 128

// ---------------- scratch ----------------
__device__ float g_sln [N_TOK * CS];
__device__ float g_alnr[N_TOK * CA];
__device__ float g_aln [N_TOK * CA];
__device__ float g_t1  [N_TOK * CA];
__device__ float g_t2  [N_TOK * CA];
__device__ float g_q   [N_TOK * CA];
__device__ float g_k   [N_TOK * CA];
__device__ float g_v   [N_TOK * CA];
__device__ float g_g   [N_TOK * CA];
__device__ float g_o   [N_TOK * CA];
__device__ float g_bias[NH * NBW * NQW * NKW];

// ---------------- LayerNorm kernels ----------------
__global__ __launch_bounds__(256) void ln_s_kernel(const float* __restrict__ s,
                                                   const float* __restrict__ gamma,
                                                   float* __restrict__ out)
{
    int row  = blockIdx.x * 8 + (threadIdx.x >> 5);
    int lane = threadIdx.x & 31;
    const float* x = s + (size_t)row * CS;
    float v[12];
    float sum = 0.f;
#pragma unroll
    for (int i = 0; i < 12; i++) { v[i] = x[lane + 32 * i]; sum += v[i]; }
#pragma unroll
    for (int o = 16; o; o >>= 1) sum += __shfl_xor_sync(0xffffffffu, sum, o);
    float m = sum * (1.0f / CS);
    float ss = 0.f;
#pragma unroll
    for (int i = 0; i < 12; i++) { float d = v[i] - m; ss += d * d; }
#pragma unroll
    for (int o = 16; o; o >>= 1) ss += __shfl_xor_sync(0xffffffffu, ss, o);
    float inv = rsqrtf(ss * (1.0f / CS) + 1e-5f);
    float* op = out + (size_t)row * CS;
#pragma unroll
    for (int i = 0; i < 12; i++)
        op[lane + 32 * i] = (v[i] - m) * inv * gamma[lane + 32 * i];
}

__global__ __launch_bounds__(256) void ln_a_kernel(const float* __restrict__ a,
                                                   float* __restrict__ out)
{
    int row  = blockIdx.x * 8 + (threadIdx.x >> 5);
    int lane = threadIdx.x & 31;
    const float* x = a + (size_t)row * CA;
    float v[24];
    float sum = 0.f;
#pragma unroll
    for (int i = 0; i < 24; i++) { v[i] = x[lane + 32 * i]; sum += v[i]; }
#pragma unroll
    for (int o = 16; o; o >>= 1) sum += __shfl_xor_sync(0xffffffffu, sum, o);
    float m = sum * (1.0f / CA);
    float ss = 0.f;
#pragma unroll
    for (int i = 0; i < 24; i++) { float d = v[i] - m; ss += d * d; }
#pragma unroll
    for (int o = 16; o; o >>= 1) ss += __shfl_xor_sync(0xffffffffu, ss, o);
    float inv = rsqrtf(ss * (1.0f / CA) + 1e-5f);
    float* op = out + (size_t)row * CA;
#pragma unroll
    for (int i = 0; i < 24; i++)
        op[lane + 32 * i] = (v[i] - m) * inv;
}

// ---------------- TF32 helpers ----------------
__device__ __forceinline__ uint32_t f2tf(float x)
{
    uint32_t r;
    asm("cvt.rna.tf32.f32 %0, %1;" : "=r"(r) : "f"(x));
    return r;
}

__device__ __forceinline__ void mma8(float* c, const uint32_t* a, const uint32_t* b)
{
    asm volatile("mma.sync.aligned.m16n8k8.row.col.f32.tf32.tf32.f32 "
                 "{%0,%1,%2,%3}, {%4,%5,%6,%7}, {%8,%9}, {%0,%1,%2,%3};"
                 : "+f"(c[0]), "+f"(c[1]), "+f"(c[2]), "+f"(c[3])
                 : "r"(a[0]), "r"(a[1]), "r"(a[2]), "r"(a[3]),
                   "r"(b[0]), "r"(b[1]));
}

// ---------------- TF32 tensor-core GEMM (unchanged from R3) ----------------
#define AS_STRIDE 136
#define BS_STRIDE 72

__global__ __launch_bounds__(256) void tgemm_k(const float* __restrict__ A,
                                               const float* __restrict__ A2,
                                               const float* __restrict__ B,
                                               const float* __restrict__ bias,
                                               const float* __restrict__ emul,
                                               float* __restrict__ C,
                                               int K, int act)
{
    __shared__ uint32_t As[16 * AS_STRIDE];
    __shared__ uint32_t Bs[16 * BS_STRIDE];

    int tid = threadIdx.x;
    int wid = tid >> 5, lane = tid & 31;
    int warp_m = wid >> 1, warp_n = wid & 1;
    int group = lane >> 2, tg = lane & 3;
    int row0 = blockIdx.y * 128;
    int col0 = blockIdx.x * 64;

    int arow = tid >> 1, akp = (tid & 1) * 8;
    int brow = tid >> 4, bcol = (tid & 15) * 4;

    const float* Abase  = A  + (size_t)(row0 + arow) * K;
    const float* A2base = A2 ? A2 + (size_t)(row0 + arow) * K : nullptr;

    float acc[2][4][4];
#pragma unroll
    for (int mt = 0; mt < 2; mt++)
#pragma unroll
        for (int nt = 0; nt < 4; nt++)
#pragma unroll
            for (int r = 0; r < 4; r++) acc[mt][nt][r] = 0.f;

    {
        float4 va0 = *(const float4*)(Abase + akp);
        float4 va1 = *(const float4*)(Abase + akp + 4);
        if (A2base) {
            float4 w0 = *(const float4*)(A2base + akp);
            float4 w1 = *(const float4*)(A2base + akp + 4);
            va0.x *= w0.x; va0.y *= w0.y; va0.z *= w0.z; va0.w *= w0.w;
            va1.x *= w1.x; va1.y *= w1.y; va1.z *= w1.z; va1.w *= w1.w;
        }
        float4 vb = *(const float4*)(B + (size_t)brow * 768 + col0 + bcol);
        float av[8] = {va0.x, va0.y, va0.z, va0.w, va1.x, va1.y, va1.z, va1.w};
#pragma unroll
        for (int i = 0; i < 8; i++) As[(akp + i) * AS_STRIDE + arow] = f2tf(av[i]);
        float bv[4] = {vb.x, vb.y, vb.z, vb.w};
#pragma unroll
        for (int i = 0; i < 4; i++) Bs[brow * BS_STRIDE + bcol + i] = f2tf(bv[i]);
    }

    for (int k0 = 0; k0 < K; k0 += 16) {
        __syncthreads();
        bool has_next = (k0 + 16) < K;
        float4 va0, va1, vb;
        if (has_next) {
            va0 = *(const float4*)(Abase + k0 + 16 + akp);
            va1 = *(const float4*)(Abase + k0 + 16 + akp + 4);
            if (A2base) {
                float4 w0 = *(const float4*)(A2base + k0 + 16 + akp);
                float4 w1 = *(const float4*)(A2base + k0 + 16 + akp + 4);
                va0.x *= w0.x; va0.y *= w0.y; va0.z *= w0.z; va0.w *= w0.w;
                va1.x *= w1.x; va1.y *= w1.y; va1.z *= w1.z; va1.w *= w1.w;
            }
            vb = *(const float4*)(B + (size_t)(k0 + 16 + brow) * 768 + col0 + bcol);
        }

#pragma unroll
        for (int kc = 0; kc < 2; kc++) {
            int kb = kc * 8;
            uint32_t afr[2][4];
#pragma unroll
            for (int mt = 0; mt < 2; mt++) {
                int m = warp_m * 32 + mt * 16 + group;
                afr[mt][0] = As[(kb + tg) * AS_STRIDE + m];
                afr[mt][1] = As[(kb + tg) * AS_STRIDE + m + 8];
                afr[mt][2] = As[(kb + tg + 4) * AS_STRIDE + m];
                afr[mt][3] = As[(kb + tg + 4) * AS_STRIDE + m + 8];
            }
            uint32_t bfr[4][2];
#pragma unroll
            for (int nt = 0; nt < 4; nt++) {
                int n = warp_n * 32 + nt * 8 + group;
                bfr[nt][0] = Bs[(kb + tg) * BS_STRIDE + n];
                bfr[nt][1] = Bs[(kb + tg + 4) * BS_STRIDE + n];
            }
#pragma unroll
            for (int mt = 0; mt < 2; mt++)
#pragma unroll
                for (int nt = 0; nt < 4; nt++)
                    mma8(acc[mt][nt], afr[mt], bfr[nt]);
        }

        __syncthreads();
        if (has_next) {
            float av[8] = {va0.x, va0.y, va0.z, va0.w, va1.x, va1.y, va1.z, va1.w};
#pragma unroll
            for (int i = 0; i < 8; i++) As[(akp + i) * AS_STRIDE + arow] = f2tf(av[i]);
            float bv[4] = {vb.x, vb.y, vb.z, vb.w};
#pragma unroll
            for (int i = 0; i < 4; i++) Bs[brow * BS_STRIDE + bcol + i] = f2tf(bv[i]);
        }
    }

#pragma unroll
    for (int mt = 0; mt < 2; mt++) {
#pragma unroll
        for (int nt = 0; nt < 4; nt++) {
            int col = col0 + warp_n * 32 + nt * 8 + tg * 2;
            float b0 = bias ? bias[col]     : 0.f;
            float b1 = bias ? bias[col + 1] : 0.f;
#pragma unroll
            for (int half = 0; half < 2; half++) {
                int row = row0 + warp_m * 32 + mt * 16 + group + half * 8;
                float v0 = acc[mt][nt][half * 2 + 0] + b0;
                float v1 = acc[mt][nt][half * 2 + 1] + b1;
                if (act == 1) {
                    v0 = 1.f / (1.f + expf(-v0));
                    v1 = 1.f / (1.f + expf(-v1));
                }
                if (emul) {
                    v0 *= emul[(size_t)row * 768 + col];
                    v1 *= emul[(size_t)row * 768 + col + 1];
                }
                float2 r = make_float2(v0, v1);
                *(float2*)&C[(size_t)row * 768 + col] = r;
            }
        }
    }
}

// ---------------- bias = LN(z)*gamma @ wz as fused LN + TF32 GEMM ----------------
// One CTA = 128 z-vectors (M=128), K=128, N=16. 256 threads, 8 warps.
#define ZAS 132                    // A stage stride (128 + 4)
#define ZBS 24                     // B stage stride (16 + 8)
#define BIAS2_SMEM ((128 * ZAS + 128 * ZBS) * 4)
__global__ __launch_bounds__(256, 2) void bias2_kernel(const float* __restrict__ z,
                                                       const float* __restrict__ gamma,
                                                       const float* __restrict__ wz,
                                                       float* __restrict__ out)
{
    extern __shared__ uint32_t dyn[];
    uint32_t* As = dyn;              // [128 rows][ZAS] tf32, row-major (m, k)
    uint32_t* Bs = dyn + 128 * ZAS;  // [128 k][ZBS] tf32
    float*    st = (float*)dyn;      // alias after mma: [16][129]

    int tid = threadIdx.x;
    int wid = tid >> 5, lane = tid & 31;
    int blk = blockIdx.x;

    // stage wz (read fully coalesced: idx == c*16+h linear)
    for (int idx = tid; idx < 2048; idx += 256) {
        int c = idx >> 4, h = idx & 15;
        Bs[c * ZBS + h] = f2tf(wz[idx]);
    }

    float4 g4 = *(const float4*)(gamma + lane * 4);

    // batched row loads: warp handles rows wid + 8*i, MLP=16
    const float* zbase = z + ((size_t)blk * 128 + wid) * CZ + lane * 4;
    float4 rv[16];
#pragma unroll
    for (int i = 0; i < 16; i++)
        rv[i] = *(const float4*)(zbase + (size_t)i * 8 * CZ);

#pragma unroll
    for (int i = 0; i < 16; i++) {
        int r = wid + 8 * i;
        float4 x = rv[i];
        float sum = x.x + x.y + x.z + x.w;
#pragma unroll
        for (int o = 16; o; o >>= 1) sum += __shfl_xor_sync(0xffffffffu, sum, o);
        float m = sum * (1.0f / CZ);
        float d0 = x.x - m, d1 = x.y - m, d2 = x.z - m, d3 = x.w - m;
        float ss = d0 * d0 + d1 * d1 + d2 * d2 + d3 * d3;
#pragma unroll
        for (int o = 16; o; o >>= 1) ss += __shfl_xor_sync(0xffffffffu, ss, o);
        float inv = rsqrtf(ss * (1.0f / CZ) + 1e-5f);
        uint4 p;
        p.x = f2tf(d0 * inv * g4.x);
        p.y = f2tf(d1 * inv * g4.y);
        p.z = f2tf(d2 * inv * g4.z);
        p.w = f2tf(d3 * inv * g4.w);
        *(uint4*)&As[r * ZAS + lane * 4] = p;
    }
    __syncthreads();

    // mma: warp wid -> rows m0..m0+15, n = 16 (2 n-tiles)
    int group = lane >> 2, tg = lane & 3;
    int m0 = wid * 16;
    float acc[2][4];
#pragma unroll
    for (int nt = 0; nt < 2; nt++)
#pragma unroll
        for (int r = 0; r < 4; r++) acc[nt][r] = 0.f;

#pragma unroll
    for (int ks = 0; ks < 16; ks++) {
        int kb = ks * 8;
        uint32_t a[4];
        a[0] = As[(m0 + group)     * ZAS + kb + tg];
        a[1] = As[(m0 + group + 8) * ZAS + kb + tg];
        a[2] = As[(m0 + group)     * ZAS + kb + tg + 4];
        a[3] = As[(m0 + group + 8) * ZAS + kb + tg + 4];
        uint32_t b0[2], b1[2];
        b0[0] = Bs[(kb + tg)     * ZBS + group];
        b0[1] = Bs[(kb + tg + 4) * ZBS + group];
        b1[0] = Bs[(kb + tg)     * ZBS + 8 + group];
        b1[1] = Bs[(kb + tg + 4) * ZBS + 8 + group];
        mma8(acc[0], a, b0);
        mma8(acc[1], a, b1);
    }
    __syncthreads();

    // scatter acc to st[h][m], then coalesced global write
#pragma unroll
    for (int nt = 0; nt < 2; nt++)
#pragma unroll
        for (int half = 0; half < 2; half++) {
            int m  = m0 + group + half * 8;
            int h0 = nt * 8 + tg * 2;
            st[h0       * 129 + m] = acc[nt][half * 2 + 0];
            st[(h0 + 1) * 129 + m] = acc[nt][half * 2 + 1];
        }
    __syncthreads();

    int wwin = blk >> 5;
    int rembase = (blk & 31) * 128;
#pragma unroll
    for (int i = 0; i < 8; i++) {
        int idx = tid + 256 * i;
        int h = idx >> 7, m = idx & 127;
        out[((size_t)(wwin * 16 + h)) * 4096 + rembase + m] = st[h * 129 + m];
    }
}

// ---------------- local attention ----------------
#define ATTN_SMEM ((32 * 48 + 2 * 128 * 52) * 4)
__global__ __launch_bounds__(256) void attn_kernel(const float* __restrict__ q,
                                                   const float* __restrict__ k,
                                                   const float* __restrict__ v,
                                                   const float* __restrict__ bias,
                                                   float* __restrict__ o)
{
    extern __shared__ float sm[];
    float* qs = sm;
    float* ks = sm + 32 * 48;
    float* vs = ks + 128 * 52;
    int w = blockIdx.x, h = blockIdx.y;
    int tid = threadIdx.x;

    for (int i = tid; i < 32 * 48; i += 256) {
        int r = i / 48, c = i - r * 48;
        qs[i] = q[(size_t)(w * 32 + r) * CA + h * 48 + c];
    }
    for (int i = tid; i < 128 * 48; i += 256) {
        int r = i / 48, c = i - r * 48;
        int tok = w * 32 - 48 + r;
        tok = tok < 0 ? 0 : (tok > 4095 ? 4095 : tok);
        ks[r * 52 + c] = k[(size_t)tok * CA + h * 48 + c];
        vs[r * 52 + c] = v[(size_t)tok * CA + h * 48 + c];
    }
    __syncthreads();

    int qi = tid >> 3, g = tid & 7;
    float4 qreg[12];
#pragma unroll
    for (int j = 0; j < 12; j++) qreg[j] = *(const float4*)&qs[qi * 48 + 4 * j];

    const float scale = 0.14433756729740643f;
    float sc[16];
    const float* bp = bias + ((size_t)(w * 16 + h) * 32 + qi) * 128;
#pragma unroll
    for (int jj = 0; jj < 16; jj++) {
        int kj = g + 8 * jj;
        int tok = w * 32 - 48 + kj;
        if (tok < 0 || tok >= 4096) { sc[jj] = -1e9f; continue; }
        const float4* kp = (const float4*)&ks[kj * 52];
        float acc = 0.f;
#pragma unroll
        for (int j = 0; j < 12; j++) {
            float4 kv = kp[j];
            acc += qreg[j].x * kv.x + qreg[j].y * kv.y
                 + qreg[j].z * kv.z + qreg[j].w * kv.w;
        }
        sc[jj] = acc * scale + bp[kj];
    }
    float mx = sc[0];
#pragma unroll
    for (int jj = 1; jj < 16; jj++) mx = fmaxf(mx, sc[jj]);
#pragma unroll
    for (int o2 = 1; o2 < 8; o2 <<= 1) mx = fmaxf(mx, __shfl_xor_sync(0xffffffffu, mx, o2));
    float sum = 0.f;
#pragma unroll
    for (int jj = 0; jj < 16; jj++) { sc[jj] = expf(sc[jj] - mx); sum += sc[jj]; }
#pragma unroll
    for (int o2 = 1; o2 < 8; o2 <<= 1) sum += __shfl_xor_sync(0xffffffffu, sum, o2);
    float inv = 1.f / sum;

    float oa[48];
#pragma unroll
    for (int d = 0; d < 48; d++) oa[d] = 0.f;
#pragma unroll
    for (int jj = 0; jj < 16; jj++) {
        float p = sc[jj] * inv;
        const float4* vp = (const float4*)&vs[(g + 8 * jj) * 52];
#pragma unroll
        for (int j = 0; j < 12; j++) {
            float4 vv = vp[j];
            oa[4 * j + 0] += p * vv.x; oa[4 * j + 1] += p * vv.y;
            oa[4 * j + 2] += p * vv.z; oa[4 * j + 3] += p * vv.w;
        }
    }
#pragma unroll
    for (int o2 = 1; o2 < 8; o2 <<= 1)
#pragma unroll
        for (int d = 0; d < 48; d++)
            oa[d] += __shfl_xor_sync(0xffffffffu, oa[d], o2);
#pragma unroll
    for (int j = 0; j < 6; j++) {
        int d = g * 6 + j;
        o[(size_t)(w * 32 + qi) * CA + h * 48 + d] = oa[d];
    }
}

// ---------------- elementwise ----------------
__global__ __launch_bounds__(256) void ew_aln_kernel(const float* __restrict__ t1,
                                                     const float* __restrict__ alnr,
                                                     const float* __restrict__ t2,
                                                     float* __restrict__ out)
{
    int i = blockIdx.x * 256 + threadIdx.x;
    if (i < N_TOK * CA)
        out[i] = (1.f / (1.f + expf(-t1[i]))) * alnr[i] + t2[i];
}

// ---------------- launch ----------------
extern "C" void kernel_launch(void* const* d_in, const int* in_sizes, int n_in,
                              void* d_out, int out_size)
{
    const float* a        = (const float*)d_in[0];
    const float* s        = (const float*)d_in[1];
    const float* z        = (const float*)d_in[2];
    const float* gamma_s  = (const float*)d_in[3];
    const float* ws       = (const float*)d_in[4];
    const float* bs       = (const float*)d_in[5];
    const float* wskip    = (const float*)d_in[6];
    const float* lnzg     = (const float*)d_in[7];
    const float* wz       = (const float*)d_in[8];
    const float* wq       = (const float*)d_in[9];
    const float* bq       = (const float*)d_in[10];
    const float* wk       = (const float*)d_in[11];
    const float* wv       = (const float*)d_in[12];
    const float* wg       = (const float*)d_in[13];
    const float* bg       = (const float*)d_in[14];
    const float* wo       = (const float*)d_in[15];
    const float* bo       = (const float*)d_in[16];
    const float* wlast    = (const float*)d_in[17];
    const float* blast    = (const float*)d_in[18];
    float* out = (float*)d_out;

    float *p_sln, *p_alnr, *p_aln, *p_t1, *p_t2, *p_q, *p_k, *p_v, *p_g, *p_o, *p_bias;
    cudaGetSymbolAddress((void**)&p_sln,  g_sln);
    cudaGetSymbolAddress((void**)&p_alnr, g_alnr);
    cudaGetSymbolAddress((void**)&p_aln,  g_aln);
    cudaGetSymbolAddress((void**)&p_t1,   g_t1);
    cudaGetSymbolAddress((void**)&p_t2,   g_t2);
    cudaGetSymbolAddress((void**)&p_q,    g_q);
    cudaGetSymbolAddress((void**)&p_k,    g_k);
    cudaGetSymbolAddress((void**)&p_v,    g_v);
    cudaGetSymbolAddress((void**)&p_g,    g_g);
    cudaGetSymbolAddress((void**)&p_o,    g_o);
    cudaGetSymbolAddress((void**)&p_bias, g_bias);

    cudaFuncSetAttribute(attn_kernel,  cudaFuncAttributeMaxDynamicSharedMemorySize, ATTN_SMEM);
    cudaFuncSetAttribute(bias2_kernel, cudaFuncAttributeMaxDynamicSharedMemorySize, BIAS2_SMEM);

    dim3 gg(12, 32);

    ln_s_kernel<<<512, 256>>>(s, gamma_s, p_sln);                               // 0
    ln_a_kernel<<<512, 256>>>(a, p_alnr);                                       // 1

    tgemm_k<<<gg, 256>>>(p_sln, nullptr, ws,    bs,      nullptr, p_t1, 384, 0);// 2
    tgemm_k<<<gg, 256>>>(p_sln, nullptr, wskip, nullptr, nullptr, p_t2, 384, 0);// 3
    ew_aln_kernel<<<12288, 256>>>(p_t1, p_alnr, p_t2, p_aln);                   // 4

    // launch index 5 -> ncu -s 5 profiles this one next round
    bias2_kernel<<<4096, 256, BIAS2_SMEM>>>(z, lnzg, wz, p_bias);               // 5

    tgemm_k<<<gg, 256>>>(p_aln, nullptr, wq, bq,      nullptr, p_q, 768, 0);    // 6
    tgemm_k<<<gg, 256>>>(p_aln, nullptr, wk, nullptr, nullptr, p_k, 768, 0);    // 7
    tgemm_k<<<gg, 256>>>(p_aln, nullptr, wv, nullptr, nullptr, p_v, 768, 0);    // 8
    tgemm_k<<<gg, 256>>>(p_aln, nullptr, wg, bg,      nullptr, p_g, 768, 1);    // 9

    attn_kernel<<<dim3(128, 16), 256, ATTN_SMEM>>>(p_q, p_k, p_v, p_bias, p_o); // 10

    tgemm_k<<<gg, 256>>>(p_o, p_g, wo, bo, nullptr, p_t2, 768, 0);              // 11
    tgemm_k<<<gg, 256>>>(s, nullptr, wlast, blast, p_t2, out, 384, 1);          // 12
}

// round 5
// speedup vs baseline: 6.7463x; 1.0639x over previous
#include <cuda_runtime.h>
#include <math.h>
#include <stdint.h>

// Problem constants
#define N_TOK 4096
#define CA 768
#define CS 384
#define CZ 128
#define NH 16
#define HD 48

// ---------------- scratch ----------------
__device__ float g_sln [N_TOK * CS];
__device__ float g_alnr[N_TOK * CA];
__device__ float g_aln [N_TOK * CA];
__device__ float g_t1  [N_TOK * CA];
__device__ float g_t2  [N_TOK * CA];
__device__ float g_q   [N_TOK * CA];
__device__ float g_k   [N_TOK * CA];
__device__ float g_v   [N_TOK * CA];
__device__ float g_g   [N_TOK * CA];
__device__ float g_o   [N_TOK * CA];
__device__ float g_bias[NH * 128 * 32 * 128];

// ---------------- LayerNorm kernels ----------------
__global__ __launch_bounds__(256) void ln_s_kernel(const float* __restrict__ s,
                                                   const float* __restrict__ gamma,
                                                   float* __restrict__ out)
{
    int row  = blockIdx.x * 8 + (threadIdx.x >> 5);
    int lane = threadIdx.x & 31;
    const float* x = s + (size_t)row * CS;
    float v[12];
    float sum = 0.f;
#pragma unroll
    for (int i = 0; i < 12; i++) { v[i] = x[lane + 32 * i]; sum += v[i]; }
#pragma unroll
    for (int o = 16; o; o >>= 1) sum += __shfl_xor_sync(0xffffffffu, sum, o);
    float m = sum * (1.0f / CS);
    float ss = 0.f;
#pragma unroll
    for (int i = 0; i < 12; i++) { float d = v[i] - m; ss += d * d; }
#pragma unroll
    for (int o = 16; o; o >>= 1) ss += __shfl_xor_sync(0xffffffffu, ss, o);
    float inv = rsqrtf(ss * (1.0f / CS) + 1e-5f);
    float* op = out + (size_t)row * CS;
#pragma unroll
    for (int i = 0; i < 12; i++)
        op[lane + 32 * i] = (v[i] - m) * inv * gamma[lane + 32 * i];
}

__global__ __launch_bounds__(256) void ln_a_kernel(const float* __restrict__ a,
                                                   float* __restrict__ out)
{
    int row  = blockIdx.x * 8 + (threadIdx.x >> 5);
    int lane = threadIdx.x & 31;
    const float* x = a + (size_t)row * CA;
    float v[24];
    float sum = 0.f;
#pragma unroll
    for (int i = 0; i < 24; i++) { v[i] = x[lane + 32 * i]; sum += v[i]; }
#pragma unroll
    for (int o = 16; o; o >>= 1) sum += __shfl_xor_sync(0xffffffffu, sum, o);
    float m = sum * (1.0f / CA);
    float ss = 0.f;
#pragma unroll
    for (int i = 0; i < 24; i++) { float d = v[i] - m; ss += d * d; }
#pragma unroll
    for (int o = 16; o; o >>= 1) ss += __shfl_xor_sync(0xffffffffu, ss, o);
    float inv = rsqrtf(ss * (1.0f / CA) + 1e-5f);
    float* op = out + (size_t)row * CA;
#pragma unroll
    for (int i = 0; i < 24; i++)
        op[lane + 32 * i] = (v[i] - m) * inv;
}

// ---------------- TF32 helpers ----------------
__device__ __forceinline__ uint32_t f2tf(float x)
{
    uint32_t r;
    asm("cvt.rna.tf32.f32 %0, %1;" : "=r"(r) : "f"(x));
    return r;
}

__device__ __forceinline__ void mma8(float* c, const uint32_t* a, const uint32_t* b)
{
    asm volatile("mma.sync.aligned.m16n8k8.row.col.f32.tf32.tf32.f32 "
                 "{%0,%1,%2,%3}, {%4,%5,%6,%7}, {%8,%9}, {%0,%1,%2,%3};"
                 : "+f"(c[0]), "+f"(c[1]), "+f"(c[2]), "+f"(c[3])
                 : "r"(a[0]), "r"(a[1]), "r"(a[2]), "r"(a[3]),
                   "r"(b[0]), "r"(b[1]));
}

// ---------------- TF32 GEMM body: double-buffered smem + reg prefetch ----------------
// act: 0 -> acc+bias ; 1 -> sigmoid(acc+bias) [*emul] ; 2 -> sigmoid(acc+bias)*emul + emul2
#define AS_STRIDE 136
#define BS_STRIDE 72

__device__ __forceinline__ void gemm_body(const float* __restrict__ A,
                                          const float* __restrict__ A2,
                                          const float* __restrict__ B,
                                          const float* __restrict__ bias,
                                          const float* __restrict__ emul,
                                          const float* __restrict__ emul2,
                                          float* __restrict__ C,
                                          int K, int act)
{
    __shared__ uint32_t AsBuf[2][16 * AS_STRIDE];
    __shared__ uint32_t BsBuf[2][16 * BS_STRIDE];

    int tid = threadIdx.x;
    int wid = tid >> 5, lane = tid & 31;
    int warp_m = wid >> 1, warp_n = wid & 1;
    int group = lane >> 2, tg = lane & 3;
    int row0 = blockIdx.y * 128;
    int col0 = blockIdx.x * 64;

    int arow = tid >> 1, akp = (tid & 1) * 8;
    int brow = tid >> 4, bcol = (tid & 15) * 4;

    const float* Abase  = A  + (size_t)(row0 + arow) * K;
    const float* A2base = A2 ? A2 + (size_t)(row0 + arow) * K : nullptr;

    float acc[2][4][4];
#pragma unroll
    for (int mt = 0; mt < 2; mt++)
#pragma unroll
        for (int nt = 0; nt < 4; nt++)
#pragma unroll
            for (int r = 0; r < 4; r++) acc[mt][nt][r] = 0.f;

    // prologue: stage tile 0 into buffer 0
    {
        float4 va0 = *(const float4*)(Abase + akp);
        float4 va1 = *(const float4*)(Abase + akp + 4);
        if (A2base) {
            float4 w0 = *(const float4*)(A2base + akp);
            float4 w1 = *(const float4*)(A2base + akp + 4);
            va0.x *= w0.x; va0.y *= w0.y; va0.z *= w0.z; va0.w *= w0.w;
            va1.x *= w1.x; va1.y *= w1.y; va1.z *= w1.z; va1.w *= w1.w;
        }
        float4 vb = *(const float4*)(B + (size_t)brow * 768 + col0 + bcol);
        float av[8] = {va0.x, va0.y, va0.z, va0.w, va1.x, va1.y, va1.z, va1.w};
#pragma unroll
        for (int i = 0; i < 8; i++) AsBuf[0][(akp + i) * AS_STRIDE + arow] = f2tf(av[i]);
        float bv[4] = {vb.x, vb.y, vb.z, vb.w};
#pragma unroll
        for (int i = 0; i < 4; i++) BsBuf[0][brow * BS_STRIDE + bcol + i] = f2tf(bv[i]);
    }

    int p = 0;
    for (int k0 = 0; k0 < K; k0 += 16) {
        __syncthreads();   // buffer p staged; previous reads of buffer 1-p done
        const uint32_t* As = AsBuf[p];
        const uint32_t* Bs = BsBuf[p];
        uint32_t* Asw = AsBuf[1 - p];
        uint32_t* Bsw = BsBuf[1 - p];

        bool has_next = (k0 + 16) < K;
        float4 va0, va1, vb;
        if (has_next) {
            va0 = *(const float4*)(Abase + k0 + 16 + akp);
            va1 = *(const float4*)(Abase + k0 + 16 + akp + 4);
            if (A2base) {
                float4 w0 = *(const float4*)(A2base + k0 + 16 + akp);
                float4 w1 = *(const float4*)(A2base + k0 + 16 + akp + 4);
                va0.x *= w0.x; va0.y *= w0.y; va0.z *= w0.z; va0.w *= w0.w;
                va1.x *= w1.x; va1.y *= w1.y; va1.z *= w1.z; va1.w *= w1.w;
            }
            vb = *(const float4*)(B + (size_t)(k0 + 16 + brow) * 768 + col0 + bcol);
        }

#pragma unroll
        for (int kc = 0; kc < 2; kc++) {
            int kb = kc * 8;
            uint32_t afr[2][4];
#pragma unroll
            for (int mt = 0; mt < 2; mt++) {
                int m = warp_m * 32 + mt * 16 + group;
                afr[mt][0] = As[(kb + tg) * AS_STRIDE + m];
                afr[mt][1] = As[(kb + tg) * AS_STRIDE + m + 8];
                afr[mt][2] = As[(kb + tg + 4) * AS_STRIDE + m];
                afr[mt][3] = As[(kb + tg + 4) * AS_STRIDE + m + 8];
            }
            uint32_t bfr[4][2];
#pragma unroll
            for (int nt = 0; nt < 4; nt++) {
                int n = warp_n * 32 + nt * 8 + group;
                bfr[nt][0] = Bs[(kb + tg) * BS_STRIDE + n];
                bfr[nt][1] = Bs[(kb + tg + 4) * BS_STRIDE + n];
            }
#pragma unroll
            for (int mt = 0; mt < 2; mt++)
#pragma unroll
                for (int nt = 0; nt < 4; nt++)
                    mma8(acc[mt][nt], afr[mt], bfr[nt]);
        }

        if (has_next) {
            float av[8] = {va0.x, va0.y, va0.z, va0.w, va1.x, va1.y, va1.z, va1.w};
#pragma unroll
            for (int i = 0; i < 8; i++) Asw[(akp + i) * AS_STRIDE + arow] = f2tf(av[i]);
            float bv[4] = {vb.x, vb.y, vb.z, vb.w};
#pragma unroll
            for (int i = 0; i < 4; i++) Bsw[brow * BS_STRIDE + bcol + i] = f2tf(bv[i]);
        }
        p ^= 1;
    }

    // epilogue
#pragma unroll
    for (int mt = 0; mt < 2; mt++) {
#pragma unroll
        for (int nt = 0; nt < 4; nt++) {
            int col = col0 + warp_n * 32 + nt * 8 + tg * 2;
            float b0 = bias ? bias[col]     : 0.f;
            float b1 = bias ? bias[col + 1] : 0.f;
#pragma unroll
            for (int half = 0; half < 2; half++) {
                int row = row0 + warp_m * 32 + mt * 16 + group + half * 8;
                float v0 = acc[mt][nt][half * 2 + 0] + b0;
                float v1 = acc[mt][nt][half * 2 + 1] + b1;
                if (act >= 1) {
                    v0 = 1.f / (1.f + expf(-v0));
                    v1 = 1.f / (1.f + expf(-v1));
                }
                if (emul) {
                    v0 *= emul[(size_t)row * 768 + col];
                    v1 *= emul[(size_t)row * 768 + col + 1];
                }
                if (act == 2) {
                    v0 += emul2[(size_t)row * 768 + col];
                    v1 += emul2[(size_t)row * 768 + col + 1];
                }
                float2 r = make_float2(v0, v1);
                *(float2*)&C[(size_t)row * 768 + col] = r;
            }
        }
    }
}

__global__ __launch_bounds__(256) void tgemm_k(const float* __restrict__ A,
                                               const float* __restrict__ A2,
                                               const float* __restrict__ B,
                                               const float* __restrict__ bias,
                                               const float* __restrict__ emul,
                                               const float* __restrict__ emul2,
                                               float* __restrict__ C,
                                               int K, int act)
{
    gemm_body(A, A2, B, bias, emul, emul2, C, K, act);
}

// batched Q/K/V/G projection: blockIdx.z selects weight/bias/act/output
__global__ __launch_bounds__(256) void tgemm_qkvg(const float* __restrict__ aln,
                                                  const float* __restrict__ wq,
                                                  const float* __restrict__ wk,
                                                  const float* __restrict__ wv,
                                                  const float* __restrict__ wg,
                                                  const float* __restrict__ bq,
                                                  const float* __restrict__ bg,
                                                  float* __restrict__ q,
                                                  float* __restrict__ k,
                                                  float* __restrict__ v,
                                                  float* __restrict__ g)
{
    int zi = blockIdx.z;
    const float* B    = (zi == 0) ? wq : (zi == 1) ? wk : (zi == 2) ? wv : wg;
    const float* bias = (zi == 0) ? bq : (zi == 3) ? bg : nullptr;
    float* C          = (zi == 0) ? q  : (zi == 1) ? k  : (zi == 2) ? v  : g;
    int act           = (zi == 3) ? 1 : 0;
    gemm_body(aln, nullptr, B, bias, nullptr, nullptr, C, 768, act);
}

// ---------------- bias = LN(z)*gamma @ wz as fused LN + TF32 GEMM ----------------
#define ZAS 132
#define ZBS 24
#define BIAS2_SMEM ((128 * ZAS + 128 * ZBS) * 4)
__global__ __launch_bounds__(256, 2) void bias2_kernel(const float* __restrict__ z,
                                                       const float* __restrict__ gamma,
                                                       const float* __restrict__ wz,
                                                       float* __restrict__ out)
{
    extern __shared__ uint32_t dyn[];
    uint32_t* As = dyn;
    uint32_t* Bs = dyn + 128 * ZAS;
    float*    st = (float*)dyn;

    int tid = threadIdx.x;
    int wid = tid >> 5, lane = tid & 31;
    int blk = blockIdx.x;

    for (int idx = tid; idx < 2048; idx += 256) {
        int c = idx >> 4, h = idx & 15;
        Bs[c * ZBS + h] = f2tf(wz[idx]);
    }

    float4 g4 = *(const float4*)(gamma + lane * 4);

    const float* zbase = z + ((size_t)blk * 128 + wid) * CZ + lane * 4;
    float4 rv[16];
#pragma unroll
    for (int i = 0; i < 16; i++)
        rv[i] = *(const float4*)(zbase + (size_t)i * 8 * CZ);

#pragma unroll
    for (int i = 0; i < 16; i++) {
        int r = wid + 8 * i;
        float4 x = rv[i];
        float sum = x.x + x.y + x.z + x.w;
#pragma unroll
        for (int o = 16; o; o >>= 1) sum += __shfl_xor_sync(0xffffffffu, sum, o);
        float m = sum * (1.0f / CZ);
        float d0 = x.x - m, d1 = x.y - m, d2 = x.z - m, d3 = x.w - m;
        float ss = d0 * d0 + d1 * d1 + d2 * d2 + d3 * d3;
#pragma unroll
        for (int o = 16; o; o >>= 1) ss += __shfl_xor_sync(0xffffffffu, ss, o);
        float inv = rsqrtf(ss * (1.0f / CZ) + 1e-5f);
        uint4 pk;
        pk.x = f2tf(d0 * inv * g4.x);
        pk.y = f2tf(d1 * inv * g4.y);
        pk.z = f2tf(d2 * inv * g4.z);
        pk.w = f2tf(d3 * inv * g4.w);
        *(uint4*)&As[r * ZAS + lane * 4] = pk;
    }
    __syncthreads();

    int group = lane >> 2, tg = lane & 3;
    int m0 = wid * 16;
    float acc[2][4];
#pragma unroll
    for (int nt = 0; nt < 2; nt++)
#pragma unroll
        for (int r = 0; r < 4; r++) acc[nt][r] = 0.f;

#pragma unroll
    for (int ks = 0; ks < 16; ks++) {
        int kb = ks * 8;
        uint32_t a[4];
        a[0] = As[(m0 + group)     * ZAS + kb + tg];
        a[1] = As[(m0 + group + 8) * ZAS + kb + tg];
        a[2] = As[(m0 + group)     * ZAS + kb + tg + 4];
        a[3] = As[(m0 + group + 8) * ZAS + kb + tg + 4];
        uint32_t b0[2], b1[2];
        b0[0] = Bs[(kb + tg)     * ZBS + group];
        b0[1] = Bs[(kb + tg + 4) * ZBS + group];
        b1[0] = Bs[(kb + tg)     * ZBS + 8 + group];
        b1[1] = Bs[(kb + tg + 4) * ZBS + 8 + group];
        mma8(acc[0], a, b0);
        mma8(acc[1], a, b1);
    }
    __syncthreads();

#pragma unroll
    for (int nt = 0; nt < 2; nt++)
#pragma unroll
        for (int half = 0; half < 2; half++) {
            int m  = m0 + group + half * 8;
            int h0 = nt * 8 + tg * 2;
            st[h0       * 129 + m] = acc[nt][half * 2 + 0];
            st[(h0 + 1) * 129 + m] = acc[nt][half * 2 + 1];
        }
    __syncthreads();

    int wwin = blk >> 5;
    int rembase = (blk & 31) * 128;
#pragma unroll
    for (int i = 0; i < 8; i++) {
        int idx = tid + 256 * i;
        int h = idx >> 7, m = idx & 127;
        out[((size_t)(wwin * 16 + h)) * 4096 + rembase + m] = st[h * 129 + m];
    }
}

// ---------------- local attention ----------------
#define ATTN_SMEM ((32 * 48 + 2 * 128 * 52) * 4)
__global__ __launch_bounds__(256) void attn_kernel(const float* __restrict__ q,
                                                   const float* __restrict__ k,
                                                   const float* __restrict__ v,
                                                   const float* __restrict__ bias,
                                                   float* __restrict__ o)
{
    extern __shared__ float sm[];
    float* qs = sm;
    float* ks = sm + 32 * 48;
    float* vs = ks + 128 * 52;
    int w = blockIdx.x, h = blockIdx.y;
    int tid = threadIdx.x;

    for (int i = tid; i < 32 * 48; i += 256) {
        int r = i / 48, c = i - r * 48;
        qs[i] = q[(size_t)(w * 32 + r) * CA + h * 48 + c];
    }
    for (int i = tid; i < 128 * 48; i += 256) {
        int r = i / 48, c = i - r * 48;
        int tok = w * 32 - 48 + r;
        tok = tok < 0 ? 0 : (tok > 4095 ? 4095 : tok);
        ks[r * 52 + c] = k[(size_t)tok * CA + h * 48 + c];
        vs[r * 52 + c] = v[(size_t)tok * CA + h * 48 + c];
    }
    __syncthreads();

    int qi = tid >> 3, g = tid & 7;
    float4 qreg[12];
#pragma unroll
    for (int j = 0; j < 12; j++) qreg[j] = *(const float4*)&qs[qi * 48 + 4 * j];

    const float scale = 0.14433756729740643f;
    float sc[16];
    const float* bp = bias + ((size_t)(w * 16 + h) * 32 + qi) * 128;
#pragma unroll
    for (int jj = 0; jj < 16; jj++) {
        int kj = g + 8 * jj;
        int tok = w * 32 - 48 + kj;
        if (tok < 0 || tok >= 4096) { sc[jj] = -1e9f; continue; }
        const float4* kp = (const float4*)&ks[kj * 52];
        float acc = 0.f;
#pragma unroll
        for (int j = 0; j < 12; j++) {
            float4 kv = kp[j];
            acc += qreg[j].x * kv.x + qreg[j].y * kv.y
                 + qreg[j].z * kv.z + qreg[j].w * kv.w;
        }
        sc[jj] = acc * scale + bp[kj];
    }
    float mx = sc[0];
#pragma unroll
    for (int jj = 1; jj < 16; jj++) mx = fmaxf(mx, sc[jj]);
#pragma unroll
    for (int o2 = 1; o2 < 8; o2 <<= 1) mx = fmaxf(mx, __shfl_xor_sync(0xffffffffu, mx, o2));
    float sum = 0.f;
#pragma unroll
    for (int jj = 0; jj < 16; jj++) { sc[jj] = expf(sc[jj] - mx); sum += sc[jj]; }
#pragma unroll
    for (int o2 = 1; o2 < 8; o2 <<= 1) sum += __shfl_xor_sync(0xffffffffu, sum, o2);
    float inv = 1.f / sum;

    float oa[48];
#pragma unroll
    for (int d = 0; d < 48; d++) oa[d] = 0.f;
#pragma unroll
    for (int jj = 0; jj < 16; jj++) {
        float p = sc[jj] * inv;
        const float4* vp = (const float4*)&vs[(g + 8 * jj) * 52];
#pragma unroll
        for (int j = 0; j < 12; j++) {
            float4 vv = vp[j];
            oa[4 * j + 0] += p * vv.x; oa[4 * j + 1] += p * vv.y;
            oa[4 * j + 2] += p * vv.z; oa[4 * j + 3] += p * vv.w;
        }
    }
#pragma unroll
    for (int o2 = 1; o2 < 8; o2 <<= 1)
#pragma unroll
        for (int d = 0; d < 48; d++)
            oa[d] += __shfl_xor_sync(0xffffffffu, oa[d], o2);
#pragma unroll
    for (int j = 0; j < 6; j++) {
        int d = g * 6 + j;
        o[(size_t)(w * 32 + qi) * CA + h * 48 + d] = oa[d];
    }
}

// ---------------- launch ----------------
extern "C" void kernel_launch(void* const* d_in, const int* in_sizes, int n_in,
                              void* d_out, int out_size)
{
    const float* a        = (const float*)d_in[0];
    const float* s        = (const float*)d_in[1];
    const float* z        = (const float*)d_in[2];
    const float* gamma_s  = (const float*)d_in[3];
    const float* ws       = (const float*)d_in[4];
    const float* bs       = (const float*)d_in[5];
    const float* wskip    = (const float*)d_in[6];
    const float* lnzg     = (const float*)d_in[7];
    const float* wz       = (const float*)d_in[8];
    const float* wq       = (const float*)d_in[9];
    const float* bq       = (const float*)d_in[10];
    const float* wk       = (const float*)d_in[11];
    const float* wv       = (const float*)d_in[12];
    const float* wg       = (const float*)d_in[13];
    const float* bg       = (const float*)d_in[14];
    const float* wo       = (const float*)d_in[15];
    const float* bo       = (const float*)d_in[16];
    const float* wlast    = (const float*)d_in[17];
    const float* blast    = (const float*)d_in[18];
    float* out = (float*)d_out;

    float *p_sln, *p_alnr, *p_aln, *p_t2, *p_q, *p_k, *p_v, *p_g, *p_o, *p_bias;
    cudaGetSymbolAddress((void**)&p_sln,  g_sln);
    cudaGetSymbolAddress((void**)&p_alnr, g_alnr);
    cudaGetSymbolAddress((void**)&p_aln,  g_aln);
    cudaGetSymbolAddress((void**)&p_t2,   g_t2);
    cudaGetSymbolAddress((void**)&p_q,    g_q);
    cudaGetSymbolAddress((void**)&p_k,    g_k);
    cudaGetSymbolAddress((void**)&p_v,    g_v);
    cudaGetSymbolAddress((void**)&p_g,    g_g);
    cudaGetSymbolAddress((void**)&p_o,    g_o);
    cudaGetSymbolAddress((void**)&p_bias, g_bias);

    cudaFuncSetAttribute(attn_kernel,  cudaFuncAttributeMaxDynamicSharedMemorySize, ATTN_SMEM);
    cudaFuncSetAttribute(bias2_kernel, cudaFuncAttributeMaxDynamicSharedMemorySize, BIAS2_SMEM);

    dim3 gg(12, 32);

    ln_s_kernel<<<512, 256>>>(s, gamma_s, p_sln);                                    // 0
    ln_a_kernel<<<512, 256>>>(a, p_alnr);                                            // 1

    tgemm_k<<<gg, 256>>>(p_sln, nullptr, wskip, nullptr, nullptr, nullptr,
                         p_t2, 384, 0);                                              // 2
    // aln = sigmoid(sln@ws + bs) * ln(a) + sln@wskip   (fully fused epilogue)
    tgemm_k<<<gg, 256>>>(p_sln, nullptr, ws, bs, p_alnr, p_t2, p_aln, 384, 2);       // 3

    bias2_kernel<<<4096, 256, BIAS2_SMEM>>>(z, lnzg, wz, p_bias);                    // 4

    tgemm_qkvg<<<dim3(12, 32, 4), 256>>>(p_aln, wq, wk, wv, wg, bq, bg,
                                         p_q, p_k, p_v, p_g);                        // 5

    attn_kernel<<<dim3(128, 16), 256, ATTN_SMEM>>>(p_q, p_k, p_v, p_bias, p_o);      // 6

    // t2 = (g * o) @ wo + bo
    tgemm_k<<<gg, 256>>>(p_o, p_g, wo, bo, nullptr, nullptr, p_t2, 768, 0);          // 7
    // out = sigmoid(s @ wlast + blast) * t2
    tgemm_k<<<gg, 256>>>(s, nullptr, wlast, blast, p_t2, nullptr, out, 384, 1);      // 8
}

// round 6
// speedup vs baseline: 6.8408x; 1.0140x over previous
#include <cuda_runtime.h>
#include <math.h>
#include <stdint.h>

// Problem constants
#define N_TOK 4096
#define CA 768
#define CS 384
#define CZ 128
#define NH 16
#define HD 48

// ---------------- scratch ----------------
__device__ float g_sln [N_TOK * CS];
__device__ float g_alnr[N_TOK * CA];
__device__ float g_aln [N_TOK * CA];
__device__ float g_t2  [N_TOK * CA];
__device__ float g_q   [N_TOK * CA];
__device__ float g_k   [N_TOK * CA];
__device__ float g_v   [N_TOK * CA];
__device__ float g_g   [N_TOK * CA];
__device__ float g_o   [N_TOK * CA];
__device__ float g_bias[NH * 128 * 32 * 128];

// ---------------- LayerNorm kernels ----------------
__global__ __launch_bounds__(256) void ln_s_kernel(const float* __restrict__ s,
                                                   const float* __restrict__ gamma,
                                                   float* __restrict__ out)
{
    int row  = blockIdx.x * 8 + (threadIdx.x >> 5);
    int lane = threadIdx.x & 31;
    const float* x = s + (size_t)row * CS;
    float v[12];
    float sum = 0.f;
#pragma unroll
    for (int i = 0; i < 12; i++) { v[i] = x[lane + 32 * i]; sum += v[i]; }
#pragma unroll
    for (int o = 16; o; o >>= 1) sum += __shfl_xor_sync(0xffffffffu, sum, o);
    float m = sum * (1.0f / CS);
    float ss = 0.f;
#pragma unroll
    for (int i = 0; i < 12; i++) { float d = v[i] - m; ss += d * d; }
#pragma unroll
    for (int o = 16; o; o >>= 1) ss += __shfl_xor_sync(0xffffffffu, ss, o);
    float inv = rsqrtf(ss * (1.0f / CS) + 1e-5f);
    float* op = out + (size_t)row * CS;
#pragma unroll
    for (int i = 0; i < 12; i++)
        op[lane + 32 * i] = (v[i] - m) * inv * gamma[lane + 32 * i];
}

__global__ __launch_bounds__(256) void ln_a_kernel(const float* __restrict__ a,
                                                   float* __restrict__ out)
{
    int row  = blockIdx.x * 8 + (threadIdx.x >> 5);
    int lane = threadIdx.x & 31;
    const float* x = a + (size_t)row * CA;
    float v[24];
    float sum = 0.f;
#pragma unroll
    for (int i = 0; i < 24; i++) { v[i] = x[lane + 32 * i]; sum += v[i]; }
#pragma unroll
    for (int o = 16; o; o >>= 1) sum += __shfl_xor_sync(0xffffffffu, sum, o);
    float m = sum * (1.0f / CA);
    float ss = 0.f;
#pragma unroll
    for (int i = 0; i < 24; i++) { float d = v[i] - m; ss += d * d; }
#pragma unroll
    for (int o = 16; o; o >>= 1) ss += __shfl_xor_sync(0xffffffffu, ss, o);
    float inv = rsqrtf(ss * (1.0f / CA) + 1e-5f);
    float* op = out + (size_t)row * CA;
#pragma unroll
    for (int i = 0; i < 24; i++)
        op[lane + 32 * i] = (v[i] - m) * inv;
}

// ---------------- TF32 helpers ----------------
__device__ __forceinline__ uint32_t f2tf(float x)
{
    uint32_t r;
    asm("cvt.rna.tf32.f32 %0, %1;" : "=r"(r) : "f"(x));
    return r;
}

__device__ __forceinline__ void mma8(float* c, const uint32_t* a, const uint32_t* b)
{
    asm volatile("mma.sync.aligned.m16n8k8.row.col.f32.tf32.tf32.f32 "
                 "{%0,%1,%2,%3}, {%4,%5,%6,%7}, {%8,%9}, {%0,%1,%2,%3};"
                 : "+f"(c[0]), "+f"(c[1]), "+f"(c[2]), "+f"(c[3])
                 : "r"(a[0]), "r"(a[1]), "r"(a[2]), "r"(a[3]),
                   "r"(b[0]), "r"(b[1]));
}

// ---------------- single-buffer TF32 GEMM body (R4 version, measured fastest) ----------
#define AS_STRIDE 136
#define BS_STRIDE 72

__device__ __forceinline__ void gemm_body(const float* __restrict__ A,
                                          const float* __restrict__ A2,
                                          const float* __restrict__ B,
                                          const float* __restrict__ bias,
                                          const float* __restrict__ emul,
                                          float* __restrict__ C,
                                          int K, int act)
{
    __shared__ uint32_t As[16 * AS_STRIDE];
    __shared__ uint32_t Bs[16 * BS_STRIDE];

    int tid = threadIdx.x;
    int wid = tid >> 5, lane = tid & 31;
    int warp_m = wid >> 1, warp_n = wid & 1;
    int group = lane >> 2, tg = lane & 3;
    int row0 = blockIdx.y * 128;
    int col0 = blockIdx.x * 64;

    int arow = tid >> 1, akp = (tid & 1) * 8;
    int brow = tid >> 4, bcol = (tid & 15) * 4;

    const float* Abase  = A  + (size_t)(row0 + arow) * K;
    const float* A2base = A2 ? A2 + (size_t)(row0 + arow) * K : nullptr;

    float acc[2][4][4];
#pragma unroll
    for (int mt = 0; mt < 2; mt++)
#pragma unroll
        for (int nt = 0; nt < 4; nt++)
#pragma unroll
            for (int r = 0; r < 4; r++) acc[mt][nt][r] = 0.f;

    {
        float4 va0 = *(const float4*)(Abase + akp);
        float4 va1 = *(const float4*)(Abase + akp + 4);
        if (A2base) {
            float4 w0 = *(const float4*)(A2base + akp);
            float4 w1 = *(const float4*)(A2base + akp + 4);
            va0.x *= w0.x; va0.y *= w0.y; va0.z *= w0.z; va0.w *= w0.w;
            va1.x *= w1.x; va1.y *= w1.y; va1.z *= w1.z; va1.w *= w1.w;
        }
        float4 vb = *(const float4*)(B + (size_t)brow * 768 + col0 + bcol);
        float av[8] = {va0.x, va0.y, va0.z, va0.w, va1.x, va1.y, va1.z, va1.w};
#pragma unroll
        for (int i = 0; i < 8; i++) As[(akp + i) * AS_STRIDE + arow] = f2tf(av[i]);
        float bv[4] = {vb.x, vb.y, vb.z, vb.w};
#pragma unroll
        for (int i = 0; i < 4; i++) Bs[brow * BS_STRIDE + bcol + i] = f2tf(bv[i]);
    }

    for (int k0 = 0; k0 < K; k0 += 16) {
        __syncthreads();
        bool has_next = (k0 + 16) < K;
        float4 va0, va1, vb;
        if (has_next) {
            va0 = *(const float4*)(Abase + k0 + 16 + akp);
            va1 = *(const float4*)(Abase + k0 + 16 + akp + 4);
            if (A2base) {
                float4 w0 = *(const float4*)(A2base + k0 + 16 + akp);
                float4 w1 = *(const float4*)(A2base + k0 + 16 + akp + 4);
                va0.x *= w0.x; va0.y *= w0.y; va0.z *= w0.z; va0.w *= w0.w;
                va1.x *= w1.x; va1.y *= w1.y; va1.z *= w1.z; va1.w *= w1.w;
            }
            vb = *(const float4*)(B + (size_t)(k0 + 16 + brow) * 768 + col0 + bcol);
        }

#pragma unroll
        for (int kc = 0; kc < 2; kc++) {
            int kb = kc * 8;
            uint32_t afr[2][4];
#pragma unroll
            for (int mt = 0; mt < 2; mt++) {
                int m = warp_m * 32 + mt * 16 + group;
                afr[mt][0] = As[(kb + tg) * AS_STRIDE + m];
                afr[mt][1] = As[(kb + tg) * AS_STRIDE + m + 8];
                afr[mt][2] = As[(kb + tg + 4) * AS_STRIDE + m];
                afr[mt][3] = As[(kb + tg + 4) * AS_STRIDE + m + 8];
            }
            uint32_t bfr[4][2];
#pragma unroll
            for (int nt = 0; nt < 4; nt++) {
                int n = warp_n * 32 + nt * 8 + group;
                bfr[nt][0] = Bs[(kb + tg) * BS_STRIDE + n];
                bfr[nt][1] = Bs[(kb + tg + 4) * BS_STRIDE + n];
            }
#pragma unroll
            for (int mt = 0; mt < 2; mt++)
#pragma unroll
                for (int nt = 0; nt < 4; nt++)
                    mma8(acc[mt][nt], afr[mt], bfr[nt]);
        }

        __syncthreads();
        if (has_next) {
            float av[8] = {va0.x, va0.y, va0.z, va0.w, va1.x, va1.y, va1.z, va1.w};
#pragma unroll
            for (int i = 0; i < 8; i++) As[(akp + i) * AS_STRIDE + arow] = f2tf(av[i]);
            float bv[4] = {vb.x, vb.y, vb.z, vb.w};
#pragma unroll
            for (int i = 0; i < 4; i++) Bs[brow * BS_STRIDE + bcol + i] = f2tf(bv[i]);
        }
    }

#pragma unroll
    for (int mt = 0; mt < 2; mt++) {
#pragma unroll
        for (int nt = 0; nt < 4; nt++) {
            int col = col0 + warp_n * 32 + nt * 8 + tg * 2;
            float b0 = bias ? bias[col]     : 0.f;
            float b1 = bias ? bias[col + 1] : 0.f;
#pragma unroll
            for (int half = 0; half < 2; half++) {
                int row = row0 + warp_m * 32 + mt * 16 + group + half * 8;
                float v0 = acc[mt][nt][half * 2 + 0] + b0;
                float v1 = acc[mt][nt][half * 2 + 1] + b1;
                if (act == 1) {
                    v0 = 1.f / (1.f + expf(-v0));
                    v1 = 1.f / (1.f + expf(-v1));
                }
                if (emul) {
                    v0 *= emul[(size_t)row * 768 + col];
                    v1 *= emul[(size_t)row * 768 + col + 1];
                }
                float2 r = make_float2(v0, v1);
                *(float2*)&C[(size_t)row * 768 + col] = r;
            }
        }
    }
}

__global__ __launch_bounds__(256) void tgemm_k(const float* __restrict__ A,
                                               const float* __restrict__ A2,
                                               const float* __restrict__ B,
                                               const float* __restrict__ bias,
                                               const float* __restrict__ emul,
                                               float* __restrict__ C,
                                               int K, int act)
{
    gemm_body(A, A2, B, bias, emul, C, K, act);
}

// batched Q/K/V/G projection
__global__ __launch_bounds__(256) void tgemm_qkvg(const float* __restrict__ aln,
                                                  const float* __restrict__ wq,
                                                  const float* __restrict__ wk,
                                                  const float* __restrict__ wv,
                                                  const float* __restrict__ wg,
                                                  const float* __restrict__ bq,
                                                  const float* __restrict__ bg,
                                                  float* __restrict__ q,
                                                  float* __restrict__ k,
                                                  float* __restrict__ v,
                                                  float* __restrict__ g)
{
    int zi = blockIdx.z;
    const float* B    = (zi == 0) ? wq : (zi == 1) ? wk : (zi == 2) ? wv : wg;
    const float* bias = (zi == 0) ? bq : (zi == 3) ? bg : nullptr;
    float* C          = (zi == 0) ? q  : (zi == 1) ? k  : (zi == 2) ? v  : g;
    int act           = (zi == 3) ? 1 : 0;
    gemm_body(aln, nullptr, B, bias, nullptr, C, 768, act);
}

// ---------------- dual-B adaln GEMM: shares A tile across ws and wskip ----------------
// aln = sigmoid(sln@ws + bs) * ln(a) + sln@wskip   in ONE pass over sln.
__global__ __launch_bounds__(256) void adaln_kernel(const float* __restrict__ sln,
                                                    const float* __restrict__ ws,
                                                    const float* __restrict__ wskip,
                                                    const float* __restrict__ bs,
                                                    const float* __restrict__ alnr,
                                                    float* __restrict__ aln)
{
    __shared__ uint32_t As [16 * AS_STRIDE];
    __shared__ uint32_t Bs1[16 * BS_STRIDE];
    __shared__ uint32_t Bs2[16 * BS_STRIDE];

    const int K = 384;
    int tid = threadIdx.x;
    int wid = tid >> 5, lane = tid & 31;
    int warp_m = wid >> 1, warp_n = wid & 1;
    int group = lane >> 2, tg = lane & 3;
    int row0 = blockIdx.y * 128;
    int col0 = blockIdx.x * 64;

    int arow = tid >> 1, akp = (tid & 1) * 8;
    int brow = tid >> 4, bcol = (tid & 15) * 4;

    const float* Abase = sln + (size_t)(row0 + arow) * K;

    float acc1[2][4][4], acc2[2][4][4];
#pragma unroll
    for (int mt = 0; mt < 2; mt++)
#pragma unroll
        for (int nt = 0; nt < 4; nt++)
#pragma unroll
            for (int r = 0; r < 4; r++) { acc1[mt][nt][r] = 0.f; acc2[mt][nt][r] = 0.f; }

    {
        float4 va0 = *(const float4*)(Abase + akp);
        float4 va1 = *(const float4*)(Abase + akp + 4);
        float4 vb1 = *(const float4*)(ws    + (size_t)brow * 768 + col0 + bcol);
        float4 vb2 = *(const float4*)(wskip + (size_t)brow * 768 + col0 + bcol);
        float av[8] = {va0.x, va0.y, va0.z, va0.w, va1.x, va1.y, va1.z, va1.w};
#pragma unroll
        for (int i = 0; i < 8; i++) As[(akp + i) * AS_STRIDE + arow] = f2tf(av[i]);
        float b1v[4] = {vb1.x, vb1.y, vb1.z, vb1.w};
        float b2v[4] = {vb2.x, vb2.y, vb2.z, vb2.w};
#pragma unroll
        for (int i = 0; i < 4; i++) {
            Bs1[brow * BS_STRIDE + bcol + i] = f2tf(b1v[i]);
            Bs2[brow * BS_STRIDE + bcol + i] = f2tf(b2v[i]);
        }
    }

    for (int k0 = 0; k0 < K; k0 += 16) {
        __syncthreads();
        bool has_next = (k0 + 16) < K;
        float4 va0, va1, vb1, vb2;
        if (has_next) {
            va0 = *(const float4*)(Abase + k0 + 16 + akp);
            va1 = *(const float4*)(Abase + k0 + 16 + akp + 4);
            vb1 = *(const float4*)(ws    + (size_t)(k0 + 16 + brow) * 768 + col0 + bcol);
            vb2 = *(const float4*)(wskip + (size_t)(k0 + 16 + brow) * 768 + col0 + bcol);
        }

#pragma unroll
        for (int kc = 0; kc < 2; kc++) {
            int kb = kc * 8;
            uint32_t afr[2][4];
#pragma unroll
            for (int mt = 0; mt < 2; mt++) {
                int m = warp_m * 32 + mt * 16 + group;
                afr[mt][0] = As[(kb + tg) * AS_STRIDE + m];
                afr[mt][1] = As[(kb + tg) * AS_STRIDE + m + 8];
                afr[mt][2] = As[(kb + tg + 4) * AS_STRIDE + m];
                afr[mt][3] = As[(kb + tg + 4) * AS_STRIDE + m + 8];
            }
#pragma unroll
            for (int nt = 0; nt < 4; nt++) {
                int n = warp_n * 32 + nt * 8 + group;
                uint32_t b1[2], b2[2];
                b1[0] = Bs1[(kb + tg) * BS_STRIDE + n];
                b1[1] = Bs1[(kb + tg + 4) * BS_STRIDE + n];
                b2[0] = Bs2[(kb + tg) * BS_STRIDE + n];
                b2[1] = Bs2[(kb + tg + 4) * BS_STRIDE + n];
#pragma unroll
                for (int mt = 0; mt < 2; mt++) {
                    mma8(acc1[mt][nt], afr[mt], b1);
                    mma8(acc2[mt][nt], afr[mt], b2);
                }
            }
        }

        __syncthreads();
        if (has_next) {
            float av[8] = {va0.x, va0.y, va0.z, va0.w, va1.x, va1.y, va1.z, va1.w};
#pragma unroll
            for (int i = 0; i < 8; i++) As[(akp + i) * AS_STRIDE + arow] = f2tf(av[i]);
            float b1v[4] = {vb1.x, vb1.y, vb1.z, vb1.w};
            float b2v[4] = {vb2.x, vb2.y, vb2.z, vb2.w};
#pragma unroll
            for (int i = 0; i < 4; i++) {
                Bs1[brow * BS_STRIDE + bcol + i] = f2tf(b1v[i]);
                Bs2[brow * BS_STRIDE + bcol + i] = f2tf(b2v[i]);
            }
        }
    }

#pragma unroll
    for (int mt = 0; mt < 2; mt++) {
#pragma unroll
        for (int nt = 0; nt < 4; nt++) {
            int col = col0 + warp_n * 32 + nt * 8 + tg * 2;
            float b0 = bs[col], b1 = bs[col + 1];
#pragma unroll
            for (int half = 0; half < 2; half++) {
                int row = row0 + warp_m * 32 + mt * 16 + group + half * 8;
                float s0 = 1.f / (1.f + expf(-(acc1[mt][nt][half * 2 + 0] + b0)));
                float s1 = 1.f / (1.f + expf(-(acc1[mt][nt][half * 2 + 1] + b1)));
                float r0 = s0 * alnr[(size_t)row * 768 + col]     + acc2[mt][nt][half * 2 + 0];
                float r1 = s1 * alnr[(size_t)row * 768 + col + 1] + acc2[mt][nt][half * 2 + 1];
                float2 r = make_float2(r0, r1);
                *(float2*)&aln[(size_t)row * 768 + col] = r;
            }
        }
    }
}

// ---------------- bias = LN(z)*gamma @ wz as fused LN + TF32 GEMM ----------------
#define ZAS 132
#define ZBS 24
#define BIAS2_SMEM ((128 * ZAS + 128 * ZBS) * 4)
__global__ __launch_bounds__(256, 2) void bias2_kernel(const float* __restrict__ z,
                                                       const float* __restrict__ gamma,
                                                       const float* __restrict__ wz,
                                                       float* __restrict__ out)
{
    extern __shared__ uint32_t dyn[];
    uint32_t* As = dyn;
    uint32_t* Bs = dyn + 128 * ZAS;
    float*    st = (float*)dyn;

    int tid = threadIdx.x;
    int wid = tid >> 5, lane = tid & 31;
    int blk = blockIdx.x;

    for (int idx = tid; idx < 2048; idx += 256) {
        int c = idx >> 4, h = idx & 15;
        Bs[c * ZBS + h] = f2tf(wz[idx]);
    }

    float4 g4 = *(const float4*)(gamma + lane * 4);

    const float* zbase = z + ((size_t)blk * 128 + wid) * CZ + lane * 4;
    float4 rv[16];
#pragma unroll
    for (int i = 0; i < 16; i++)
        rv[i] = *(const float4*)(zbase + (size_t)i * 8 * CZ);

#pragma unroll
    for (int i = 0; i < 16; i++) {
        int r = wid + 8 * i;
        float4 x = rv[i];
        float sum = x.x + x.y + x.z + x.w;
#pragma unroll
        for (int o = 16; o; o >>= 1) sum += __shfl_xor_sync(0xffffffffu, sum, o);
        float m = sum * (1.0f / CZ);
        float d0 = x.x - m, d1 = x.y - m, d2 = x.z - m, d3 = x.w - m;
        float ss = d0 * d0 + d1 * d1 + d2 * d2 + d3 * d3;
#pragma unroll
        for (int o = 16; o; o >>= 1) ss += __shfl_xor_sync(0xffffffffu, ss, o);
        float inv = rsqrtf(ss * (1.0f / CZ) + 1e-5f);
        uint4 pk;
        pk.x = f2tf(d0 * inv * g4.x);
        pk.y = f2tf(d1 * inv * g4.y);
        pk.z = f2tf(d2 * inv * g4.z);
        pk.w = f2tf(d3 * inv * g4.w);
        *(uint4*)&As[r * ZAS + lane * 4] = pk;
    }
    __syncthreads();

    int group = lane >> 2, tg = lane & 3;
    int m0 = wid * 16;
    float acc[2][4];
#pragma unroll
    for (int nt = 0; nt < 2; nt++)
#pragma unroll
        for (int r = 0; r < 4; r++) acc[nt][r] = 0.f;

#pragma unroll
    for (int ks = 0; ks < 16; ks++) {
        int kb = ks * 8;
        uint32_t a[4];
        a[0] = As[(m0 + group)     * ZAS + kb + tg];
        a[1] = As[(m0 + group + 8) * ZAS + kb + tg];
        a[2] = As[(m0 + group)     * ZAS + kb + tg + 4];
        a[3] = As[(m0 + group + 8) * ZAS + kb + tg + 4];
        uint32_t b0[2], b1[2];
        b0[0] = Bs[(kb + tg)     * ZBS + group];
        b0[1] = Bs[(kb + tg + 4) * ZBS + group];
        b1[0] = Bs[(kb + tg)     * ZBS + 8 + group];
        b1[1] = Bs[(kb + tg + 4) * ZBS + 8 + group];
        mma8(acc[0], a, b0);
        mma8(acc[1], a, b1);
    }
    __syncthreads();

#pragma unroll
    for (int nt = 0; nt < 2; nt++)
#pragma unroll
        for (int half = 0; half < 2; half++) {
            int m  = m0 + group + half * 8;
            int h0 = nt * 8 + tg * 2;
            st[h0       * 129 + m] = acc[nt][half * 2 + 0];
            st[(h0 + 1) * 129 + m] = acc[nt][half * 2 + 1];
        }
    __syncthreads();

    int wwin = blk >> 5;
    int rembase = (blk & 31) * 128;
#pragma unroll
    for (int i = 0; i < 8; i++) {
        int idx = tid + 256 * i;
        int h = idx >> 7, m = idx & 127;
        out[((size_t)(wwin * 16 + h)) * 4096 + rembase + m] = st[h * 129 + m];
    }
}

// ---------------- local attention ----------------
#define ATTN_SMEM ((32 * 48 + 2 * 128 * 52) * 4)
__global__ __launch_bounds__(256) void attn_kernel(const float* __restrict__ q,
                                                   const float* __restrict__ k,
                                                   const float* __restrict__ v,
                                                   const float* __restrict__ bias,
                                                   float* __restrict__ o)
{
    extern __shared__ float sm[];
    float* qs = sm;
    float* ks = sm + 32 * 48;
    float* vs = ks + 128 * 52;
    int w = blockIdx.x, h = blockIdx.y;
    int tid = threadIdx.x;

    for (int i = tid; i < 32 * 48; i += 256) {
        int r = i / 48, c = i - r * 48;
        qs[i] = q[(size_t)(w * 32 + r) * CA + h * 48 + c];
    }
    for (int i = tid; i < 128 * 48; i += 256) {
        int r = i / 48, c = i - r * 48;
        int tok = w * 32 - 48 + r;
        tok = tok < 0 ? 0 : (tok > 4095 ? 4095 : tok);
        ks[r * 52 + c] = k[(size_t)tok * CA + h * 48 + c];
        vs[r * 52 + c] = v[(size_t)tok * CA + h * 48 + c];
    }
    __syncthreads();

    int qi = tid >> 3, g = tid & 7;
    float4 qreg[12];
#pragma unroll
    for (int j = 0; j < 12; j++) qreg[j] = *(const float4*)&qs[qi * 48 + 4 * j];

    const float scale = 0.14433756729740643f;
    float sc[16];
    const float* bp = bias + ((size_t)(w * 16 + h) * 32 + qi) * 128;
#pragma unroll
    for (int jj = 0; jj < 16; jj++) {
        int kj = g + 8 * jj;
        int tok = w * 32 - 48 + kj;
        if (tok < 0 || tok >= 4096) { sc[jj] = -1e9f; continue; }
        const float4* kp = (const float4*)&ks[kj * 52];
        float acc = 0.f;
#pragma unroll
        for (int j = 0; j < 12; j++) {
            float4 kv = kp[j];
            acc += qreg[j].x * kv.x + qreg[j].y * kv.y
                 + qreg[j].z * kv.z + qreg[j].w * kv.w;
        }
        sc[jj] = acc * scale + bp[kj];
    }
    float mx = sc[0];
#pragma unroll
    for (int jj = 1; jj < 16; jj++) mx = fmaxf(mx, sc[jj]);
#pragma unroll
    for (int o2 = 1; o2 < 8; o2 <<= 1) mx = fmaxf(mx, __shfl_xor_sync(0xffffffffu, mx, o2));
    float sum = 0.f;
#pragma unroll
    for (int jj = 0; jj < 16; jj++) { sc[jj] = expf(sc[jj] - mx); sum += sc[jj]; }
#pragma unroll
    for (int o2 = 1; o2 < 8; o2 <<= 1) sum += __shfl_xor_sync(0xffffffffu, sum, o2);
    float inv = 1.f / sum;

    float oa[48];
#pragma unroll
    for (int d = 0; d < 48; d++) oa[d] = 0.f;
#pragma unroll
    for (int jj = 0; jj < 16; jj++) {
        float p = sc[jj] * inv;
        const float4* vp = (const float4*)&vs[(g + 8 * jj) * 52];
#pragma unroll
        for (int j = 0; j < 12; j++) {
            float4 vv = vp[j];
            oa[4 * j + 0] += p * vv.x; oa[4 * j + 1] += p * vv.y;
            oa[4 * j + 2] += p * vv.z; oa[4 * j + 3] += p * vv.w;
        }
    }
#pragma unroll
    for (int o2 = 1; o2 < 8; o2 <<= 1)
#pragma unroll
        for (int d = 0; d < 48; d++)
            oa[d] += __shfl_xor_sync(0xffffffffu, oa[d], o2);
#pragma unroll
    for (int j = 0; j < 6; j++) {
        int d = g * 6 + j;
        o[(size_t)(w * 32 + qi) * CA + h * 48 + d] = oa[d];
    }
}

// ---------------- launch ----------------
extern "C" void kernel_launch(void* const* d_in, const int* in_sizes, int n_in,
                              void* d_out, int out_size)
{
    const float* a        = (const float*)d_in[0];
    const float* s        = (const float*)d_in[1];
    const float* z        = (const float*)d_in[2];
    const float* gamma_s  = (const float*)d_in[3];
    const float* ws       = (const float*)d_in[4];
    const float* bs       = (const float*)d_in[5];
    const float* wskip    = (const float*)d_in[6];
    const float* lnzg     = (const float*)d_in[7];
    const float* wz       = (const float*)d_in[8];
    const float* wq       = (const float*)d_in[9];
    const float* bq       = (const float*)d_in[10];
    const float* wk       = (const float*)d_in[11];
    const float* wv       = (const float*)d_in[12];
    const float* wg       = (const float*)d_in[13];
    const float* bg       = (const float*)d_in[14];
    const float* wo       = (const float*)d_in[15];
    const float* bo       = (const float*)d_in[16];
    const float* wlast    = (const float*)d_in[17];
    const float* blast    = (const float*)d_in[18];
    float* out = (float*)d_out;

    float *p_sln, *p_alnr, *p_aln, *p_t2, *p_q, *p_k, *p_v, *p_g, *p_o, *p_bias;
    cudaGetSymbolAddress((void**)&p_sln,  g_sln);
    cudaGetSymbolAddress((void**)&p_alnr, g_alnr);
    cudaGetSymbolAddress((void**)&p_aln,  g_aln);
    cudaGetSymbolAddress((void**)&p_t2,   g_t2);
    cudaGetSymbolAddress((void**)&p_q,    g_q);
    cudaGetSymbolAddress((void**)&p_k,    g_k);
    cudaGetSymbolAddress((void**)&p_v,    g_v);
    cudaGetSymbolAddress((void**)&p_g,    g_g);
    cudaGetSymbolAddress((void**)&p_o,    g_o);
    cudaGetSymbolAddress((void**)&p_bias, g_bias);

    cudaFuncSetAttribute(attn_kernel,  cudaFuncAttributeMaxDynamicSharedMemorySize, ATTN_SMEM);
    cudaFuncSetAttribute(bias2_kernel, cudaFuncAttributeMaxDynamicSharedMemorySize, BIAS2_SMEM);

    dim3 gg(12, 32);

    ln_s_kernel<<<512, 256>>>(s, gamma_s, p_sln);                                    // 0
    ln_a_kernel<<<512, 256>>>(a, p_alnr);                                            // 1

    // aln = sigmoid(sln@ws + bs) * ln(a) + sln@wskip  (one pass over sln)
    adaln_kernel<<<gg, 256>>>(p_sln, ws, wskip, bs, p_alnr, p_aln);                  // 2

    bias2_kernel<<<4096, 256, BIAS2_SMEM>>>(z, lnzg, wz, p_bias);                    // 3

    tgemm_qkvg<<<dim3(12, 32, 4), 256>>>(p_aln, wq, wk, wv, wg, bq, bg,
                                         p_q, p_k, p_v, p_g);                        // 4

    attn_kernel<<<dim3(128, 16), 256, ATTN_SMEM>>>(p_q, p_k, p_v, p_bias, p_o);      // 5

    // t2 = (g * o) @ wo + bo
    tgemm_k<<<gg, 256>>>(p_o, p_g, wo, bo, nullptr, p_t2, 768, 0);                   // 6
    // out = sigmoid(s @ wlast + blast) * t2
    tgemm_k<<<gg, 256>>>(s, nullptr, wlast, blast, p_t2, out, 384, 1);               // 7
}

// round 7
// speedup vs baseline: 7.1716x; 1.0484x over previous
#include <cuda_runtime.h>
#include <math.h>
#include <stdint.h>

// Problem constants
#define N_TOK 4096
#define CA 768
#define CS 384
#define CZ 128
#define NH 16
#define HD 48

// ---------------- scratch ----------------
__device__ float g_sln [N_TOK * CS];
__device__ float g_alnr[N_TOK * CA];
__device__ float g_aln [N_TOK * CA];
__device__ float g_t2  [N_TOK * CA];
__device__ float g_q   [N_TOK * CA];
__device__ float g_k   [N_TOK * CA];
__device__ float g_v   [N_TOK * CA];
__device__ float g_g   [N_TOK * CA];
__device__ float g_o   [N_TOK * CA];
__device__ float g_bias[NH * 128 * 32 * 128];

// ---------------- LayerNorm kernels ----------------
__global__ __launch_bounds__(256) void ln_s_kernel(const float* __restrict__ s,
                                                   const float* __restrict__ gamma,
                                                   float* __restrict__ out)
{
    int row  = blockIdx.x * 8 + (threadIdx.x >> 5);
    int lane = threadIdx.x & 31;
    const float* x = s + (size_t)row * CS;
    float v[12];
    float sum = 0.f;
#pragma unroll
    for (int i = 0; i < 12; i++) { v[i] = x[lane + 32 * i]; sum += v[i]; }
#pragma unroll
    for (int o = 16; o; o >>= 1) sum += __shfl_xor_sync(0xffffffffu, sum, o);
    float m = sum * (1.0f / CS);
    float ss = 0.f;
#pragma unroll
    for (int i = 0; i < 12; i++) { float d = v[i] - m; ss += d * d; }
#pragma unroll
    for (int o = 16; o; o >>= 1) ss += __shfl_xor_sync(0xffffffffu, ss, o);
    float inv = rsqrtf(ss * (1.0f / CS) + 1e-5f);
    float* op = out + (size_t)row * CS;
#pragma unroll
    for (int i = 0; i < 12; i++)
        op[lane + 32 * i] = (v[i] - m) * inv * gamma[lane + 32 * i];
}

__global__ __launch_bounds__(256) void ln_a_kernel(const float* __restrict__ a,
                                                   float* __restrict__ out)
{
    int row  = blockIdx.x * 8 + (threadIdx.x >> 5);
    int lane = threadIdx.x & 31;
    const float* x = a + (size_t)row * CA;
    float v[24];
    float sum = 0.f;
#pragma unroll
    for (int i = 0; i < 24; i++) { v[i] = x[lane + 32 * i]; sum += v[i]; }
#pragma unroll
    for (int o = 16; o; o >>= 1) sum += __shfl_xor_sync(0xffffffffu, sum, o);
    float m = sum * (1.0f / CA);
    float ss = 0.f;
#pragma unroll
    for (int i = 0; i < 24; i++) { float d = v[i] - m; ss += d * d; }
#pragma unroll
    for (int o = 16; o; o >>= 1) ss += __shfl_xor_sync(0xffffffffu, ss, o);
    float inv = rsqrtf(ss * (1.0f / CA) + 1e-5f);
    float* op = out + (size_t)row * CA;
#pragma unroll
    for (int i = 0; i < 24; i++)
        op[lane + 32 * i] = (v[i] - m) * inv;
}

// ---------------- TF32 helpers ----------------
__device__ __forceinline__ uint32_t f2tf(float x)
{
    uint32_t r;
    asm("cvt.rna.tf32.f32 %0, %1;" : "=r"(r) : "f"(x));
    return r;
}

__device__ __forceinline__ void mma8(float* c, const uint32_t* a, const uint32_t* b)
{
    asm volatile("mma.sync.aligned.m16n8k8.row.col.f32.tf32.tf32.f32 "
                 "{%0,%1,%2,%3}, {%4,%5,%6,%7}, {%8,%9}, {%0,%1,%2,%3};"
                 : "+f"(c[0]), "+f"(c[1]), "+f"(c[2]), "+f"(c[3])
                 : "r"(a[0]), "r"(a[1]), "r"(a[2]), "r"(a[3]),
                   "r"(b[0]), "r"(b[1]));
}

// ---------------- BM=128 BN=128 BK=16 TF32 GEMM body ----------------
// 8 warps in 2(m)x4(n); warp tile 64x32 = 4x4 m16n8 tiles.
#define AS_STRIDE 136
#define BS2_STRIDE 136

__device__ __forceinline__ void gemm_body128(const float* __restrict__ A,
                                             const float* __restrict__ A2,
                                             const float* __restrict__ B,
                                             const float* __restrict__ bias,
                                             const float* __restrict__ emul,
                                             float* __restrict__ C,
                                             int K, int act)
{
    __shared__ uint32_t As[16 * AS_STRIDE];
    __shared__ uint32_t Bs[16 * BS2_STRIDE];

    int tid = threadIdx.x;
    int wid = tid >> 5, lane = tid & 31;
    int warp_m = wid >> 2, warp_n = wid & 3;
    int group = lane >> 2, tg = lane & 3;
    int row0 = blockIdx.y * 128;
    int col0 = blockIdx.x * 128;

    int arow = tid >> 1, akp = (tid & 1) * 8;
    int brow = tid >> 4, bcol = (tid & 15) * 8;

    const float* Abase  = A  + (size_t)(row0 + arow) * K;
    const float* A2base = A2 ? A2 + (size_t)(row0 + arow) * K : nullptr;
    const float* Bbase  = B + (size_t)brow * 768 + col0 + bcol;

    float acc[4][4][4];
#pragma unroll
    for (int mt = 0; mt < 4; mt++)
#pragma unroll
        for (int nt = 0; nt < 4; nt++)
#pragma unroll
            for (int r = 0; r < 4; r++) acc[mt][nt][r] = 0.f;

    // prologue: stage tile 0
    {
        float4 va0 = *(const float4*)(Abase + akp);
        float4 va1 = *(const float4*)(Abase + akp + 4);
        if (A2base) {
            float4 w0 = *(const float4*)(A2base + akp);
            float4 w1 = *(const float4*)(A2base + akp + 4);
            va0.x *= w0.x; va0.y *= w0.y; va0.z *= w0.z; va0.w *= w0.w;
            va1.x *= w1.x; va1.y *= w1.y; va1.z *= w1.z; va1.w *= w1.w;
        }
        float4 vb0 = *(const float4*)(Bbase);
        float4 vb1 = *(const float4*)(Bbase + 4);
        float av[8] = {va0.x, va0.y, va0.z, va0.w, va1.x, va1.y, va1.z, va1.w};
#pragma unroll
        for (int i = 0; i < 8; i++) As[(akp + i) * AS_STRIDE + arow] = f2tf(av[i]);
        float bv[8] = {vb0.x, vb0.y, vb0.z, vb0.w, vb1.x, vb1.y, vb1.z, vb1.w};
#pragma unroll
        for (int i = 0; i < 8; i++) Bs[brow * BS2_STRIDE + bcol + i] = f2tf(bv[i]);
    }

    for (int k0 = 0; k0 < K; k0 += 16) {
        __syncthreads();
        bool has_next = (k0 + 16) < K;
        float4 va0, va1, vb0, vb1;
        if (has_next) {
            va0 = *(const float4*)(Abase + k0 + 16 + akp);
            va1 = *(const float4*)(Abase + k0 + 16 + akp + 4);
            if (A2base) {
                float4 w0 = *(const float4*)(A2base + k0 + 16 + akp);
                float4 w1 = *(const float4*)(A2base + k0 + 16 + akp + 4);
                va0.x *= w0.x; va0.y *= w0.y; va0.z *= w0.z; va0.w *= w0.w;
                va1.x *= w1.x; va1.y *= w1.y; va1.z *= w1.z; va1.w *= w1.w;
            }
            vb0 = *(const float4*)(Bbase + (size_t)(k0 + 16) * 768);
            vb1 = *(const float4*)(Bbase + (size_t)(k0 + 16) * 768 + 4);
        }

#pragma unroll
        for (int kc = 0; kc < 2; kc++) {
            int kb = kc * 8;
            uint32_t afr[4][4];
#pragma unroll
            for (int mt = 0; mt < 4; mt++) {
                int m = warp_m * 64 + mt * 16 + group;
                afr[mt][0] = As[(kb + tg) * AS_STRIDE + m];
                afr[mt][1] = As[(kb + tg) * AS_STRIDE + m + 8];
                afr[mt][2] = As[(kb + tg + 4) * AS_STRIDE + m];
                afr[mt][3] = As[(kb + tg + 4) * AS_STRIDE + m + 8];
            }
            uint32_t bfr[4][2];
#pragma unroll
            for (int nt = 0; nt < 4; nt++) {
                int n = warp_n * 32 + nt * 8 + group;
                bfr[nt][0] = Bs[(kb + tg) * BS2_STRIDE + n];
                bfr[nt][1] = Bs[(kb + tg + 4) * BS2_STRIDE + n];
            }
#pragma unroll
            for (int mt = 0; mt < 4; mt++)
#pragma unroll
                for (int nt = 0; nt < 4; nt++)
                    mma8(acc[mt][nt], afr[mt], bfr[nt]);
        }

        __syncthreads();
        if (has_next) {
            float av[8] = {va0.x, va0.y, va0.z, va0.w, va1.x, va1.y, va1.z, va1.w};
#pragma unroll
            for (int i = 0; i < 8; i++) As[(akp + i) * AS_STRIDE + arow] = f2tf(av[i]);
            float bv[8] = {vb0.x, vb0.y, vb0.z, vb0.w, vb1.x, vb1.y, vb1.z, vb1.w};
#pragma unroll
            for (int i = 0; i < 8; i++) Bs[brow * BS2_STRIDE + bcol + i] = f2tf(bv[i]);
        }
    }

    // epilogue
#pragma unroll
    for (int mt = 0; mt < 4; mt++) {
#pragma unroll
        for (int nt = 0; nt < 4; nt++) {
            int col = col0 + warp_n * 32 + nt * 8 + tg * 2;
            float b0 = bias ? bias[col]     : 0.f;
            float b1 = bias ? bias[col + 1] : 0.f;
#pragma unroll
            for (int half = 0; half < 2; half++) {
                int row = row0 + warp_m * 64 + mt * 16 + group + half * 8;
                float v0 = acc[mt][nt][half * 2 + 0] + b0;
                float v1 = acc[mt][nt][half * 2 + 1] + b1;
                if (act == 1) {
                    v0 = 1.f / (1.f + expf(-v0));
                    v1 = 1.f / (1.f + expf(-v1));
                }
                if (emul) {
                    v0 *= emul[(size_t)row * 768 + col];
                    v1 *= emul[(size_t)row * 768 + col + 1];
                }
                float2 r = make_float2(v0, v1);
                *(float2*)&C[(size_t)row * 768 + col] = r;
            }
        }
    }
}

__global__ __launch_bounds__(256) void tgemm_k(const float* __restrict__ A,
                                               const float* __restrict__ A2,
                                               const float* __restrict__ B,
                                               const float* __restrict__ bias,
                                               const float* __restrict__ emul,
                                               float* __restrict__ C,
                                               int K, int act)
{
    gemm_body128(A, A2, B, bias, emul, C, K, act);
}

// batched Q/K/V/G projection
__global__ __launch_bounds__(256) void tgemm_qkvg(const float* __restrict__ aln,
                                                  const float* __restrict__ wq,
                                                  const float* __restrict__ wk,
                                                  const float* __restrict__ wv,
                                                  const float* __restrict__ wg,
                                                  const float* __restrict__ bq,
                                                  const float* __restrict__ bg,
                                                  float* __restrict__ q,
                                                  float* __restrict__ k,
                                                  float* __restrict__ v,
                                                  float* __restrict__ g)
{
    int zi = blockIdx.z;
    const float* B    = (zi == 0) ? wq : (zi == 1) ? wk : (zi == 2) ? wv : wg;
    const float* bias = (zi == 0) ? bq : (zi == 3) ? bg : nullptr;
    float* C          = (zi == 0) ? q  : (zi == 1) ? k  : (zi == 2) ? v  : g;
    int act           = (zi == 3) ? 1 : 0;
    gemm_body128(aln, nullptr, B, bias, nullptr, C, 768, act);
}

// ---------------- dual-B adaln GEMM (BN=64, proven at R6) ----------------
#define BS_STRIDE 72
__global__ __launch_bounds__(256) void adaln_kernel(const float* __restrict__ sln,
                                                    const float* __restrict__ ws,
                                                    const float* __restrict__ wskip,
                                                    const float* __restrict__ bs,
                                                    const float* __restrict__ alnr,
                                                    float* __restrict__ aln)
{
    __shared__ uint32_t As [16 * AS_STRIDE];
    __shared__ uint32_t Bs1[16 * BS_STRIDE];
    __shared__ uint32_t Bs2[16 * BS_STRIDE];

    const int K = 384;
    int tid = threadIdx.x;
    int wid = tid >> 5, lane = tid & 31;
    int warp_m = wid >> 1, warp_n = wid & 1;
    int group = lane >> 2, tg = lane & 3;
    int row0 = blockIdx.y * 128;
    int col0 = blockIdx.x * 64;

    int arow = tid >> 1, akp = (tid & 1) * 8;
    int brow = tid >> 4, bcol = (tid & 15) * 4;

    const float* Abase = sln + (size_t)(row0 + arow) * K;

    float acc1[2][4][4], acc2[2][4][4];
#pragma unroll
    for (int mt = 0; mt < 2; mt++)
#pragma unroll
        for (int nt = 0; nt < 4; nt++)
#pragma unroll
            for (int r = 0; r < 4; r++) { acc1[mt][nt][r] = 0.f; acc2[mt][nt][r] = 0.f; }

    {
        float4 va0 = *(const float4*)(Abase + akp);
        float4 va1 = *(const float4*)(Abase + akp + 4);
        float4 vb1 = *(const float4*)(ws    + (size_t)brow * 768 + col0 + bcol);
        float4 vb2 = *(const float4*)(wskip + (size_t)brow * 768 + col0 + bcol);
        float av[8] = {va0.x, va0.y, va0.z, va0.w, va1.x, va1.y, va1.z, va1.w};
#pragma unroll
        for (int i = 0; i < 8; i++) As[(akp + i) * AS_STRIDE + arow] = f2tf(av[i]);
        float b1v[4] = {vb1.x, vb1.y, vb1.z, vb1.w};
        float b2v[4] = {vb2.x, vb2.y, vb2.z, vb2.w};
#pragma unroll
        for (int i = 0; i < 4; i++) {
            Bs1[brow * BS_STRIDE + bcol + i] = f2tf(b1v[i]);
            Bs2[brow * BS_STRIDE + bcol + i] = f2tf(b2v[i]);
        }
    }

    for (int k0 = 0; k0 < K; k0 += 16) {
        __syncthreads();
        bool has_next = (k0 + 16) < K;
        float4 va0, va1, vb1, vb2;
        if (has_next) {
            va0 = *(const float4*)(Abase + k0 + 16 + akp);
            va1 = *(const float4*)(Abase + k0 + 16 + akp + 4);
            vb1 = *(const float4*)(ws    + (size_t)(k0 + 16 + brow) * 768 + col0 + bcol);
            vb2 = *(const float4*)(wskip + (size_t)(k0 + 16 + brow) * 768 + col0 + bcol);
        }

#pragma unroll
        for (int kc = 0; kc < 2; kc++) {
            int kb = kc * 8;
            uint32_t afr[2][4];
#pragma unroll
            for (int mt = 0; mt < 2; mt++) {
                int m = warp_m * 32 + mt * 16 + group;
                afr[mt][0] = As[(kb + tg) * AS_STRIDE + m];
                afr[mt][1] = As[(kb + tg) * AS_STRIDE + m + 8];
                afr[mt][2] = As[(kb + tg + 4) * AS_STRIDE + m];
                afr[mt][3] = As[(kb + tg + 4) * AS_STRIDE + m + 8];
            }
#pragma unroll
            for (int nt = 0; nt < 4; nt++) {
                int n = warp_n * 32 + nt * 8 + group;
                uint32_t b1[2], b2[2];
                b1[0] = Bs1[(kb + tg) * BS_STRIDE + n];
                b1[1] = Bs1[(kb + tg + 4) * BS_STRIDE + n];
                b2[0] = Bs2[(kb + tg) * BS_STRIDE + n];
                b2[1] = Bs2[(kb + tg + 4) * BS_STRIDE + n];
#pragma unroll
                for (int mt = 0; mt < 2; mt++) {
                    mma8(acc1[mt][nt], afr[mt], b1);
                    mma8(acc2[mt][nt], afr[mt], b2);
                }
            }
        }

        __syncthreads();
        if (has_next) {
            float av[8] = {va0.x, va0.y, va0.z, va0.w, va1.x, va1.y, va1.z, va1.w};
#pragma unroll
            for (int i = 0; i < 8; i++) As[(akp + i) * AS_STRIDE + arow] = f2tf(av[i]);
            float b1v[4] = {vb1.x, vb1.y, vb1.z, vb1.w};
            float b2v[4] = {vb2.x, vb2.y, vb2.z, vb2.w};
#pragma unroll
            for (int i = 0; i < 4; i++) {
                Bs1[brow * BS_STRIDE + bcol + i] = f2tf(b1v[i]);
                Bs2[brow * BS_STRIDE + bcol + i] = f2tf(b2v[i]);
            }
        }
    }

#pragma unroll
    for (int mt = 0; mt < 2; mt++) {
#pragma unroll
        for (int nt = 0; nt < 4; nt++) {
            int col = col0 + warp_n * 32 + nt * 8 + tg * 2;
            float b0 = bs[col], b1 = bs[col + 1];
#pragma unroll
            for (int half = 0; half < 2; half++) {
                int row = row0 + warp_m * 32 + mt * 16 + group + half * 8;
                float s0 = 1.f / (1.f + expf(-(acc1[mt][nt][half * 2 + 0] + b0)));
                float s1 = 1.f / (1.f + expf(-(acc1[mt][nt][half * 2 + 1] + b1)));
                float r0 = s0 * alnr[(size_t)row * 768 + col]     + acc2[mt][nt][half * 2 + 0];
                float r1 = s1 * alnr[(size_t)row * 768 + col + 1] + acc2[mt][nt][half * 2 + 1];
                float2 r = make_float2(r0, r1);
                *(float2*)&aln[(size_t)row * 768 + col] = r;
            }
        }
    }
}

// ---------------- bias = LN(z)*gamma @ wz as fused LN + TF32 GEMM ----------------
#define ZAS 132
#define ZBS 24
#define BIAS2_SMEM ((128 * ZAS + 128 * ZBS) * 4)
__global__ __launch_bounds__(256, 2) void bias2_kernel(const float* __restrict__ z,
                                                       const float* __restrict__ gamma,
                                                       const float* __restrict__ wz,
                                                       float* __restrict__ out)
{
    extern __shared__ uint32_t dyn[];
    uint32_t* As = dyn;
    uint32_t* Bs = dyn + 128 * ZAS;
    float*    st = (float*)dyn;

    int tid = threadIdx.x;
    int wid = tid >> 5, lane = tid & 31;
    int blk = blockIdx.x;

    for (int idx = tid; idx < 2048; idx += 256) {
        int c = idx >> 4, h = idx & 15;
        Bs[c * ZBS + h] = f2tf(wz[idx]);
    }

    float4 g4 = *(const float4*)(gamma + lane * 4);

    const float* zbase = z + ((size_t)blk * 128 + wid) * CZ + lane * 4;
    float4 rv[16];
#pragma unroll
    for (int i = 0; i < 16; i++)
        rv[i] = *(const float4*)(zbase + (size_t)i * 8 * CZ);

#pragma unroll
    for (int i = 0; i < 16; i++) {
        int r = wid + 8 * i;
        float4 x = rv[i];
        float sum = x.x + x.y + x.z + x.w;
#pragma unroll
        for (int o = 16; o; o >>= 1) sum += __shfl_xor_sync(0xffffffffu, sum, o);
        float m = sum * (1.0f / CZ);
        float d0 = x.x - m, d1 = x.y - m, d2 = x.z - m, d3 = x.w - m;
        float ss = d0 * d0 + d1 * d1 + d2 * d2 + d3 * d3;
#pragma unroll
        for (int o = 16; o; o >>= 1) ss += __shfl_xor_sync(0xffffffffu, ss, o);
        float inv = rsqrtf(ss * (1.0f / CZ) + 1e-5f);
        uint4 pk;
        pk.x = f2tf(d0 * inv * g4.x);
        pk.y = f2tf(d1 * inv * g4.y);
        pk.z = f2tf(d2 * inv * g4.z);
        pk.w = f2tf(d3 * inv * g4.w);
        *(uint4*)&As[r * ZAS + lane * 4] = pk;
    }
    __syncthreads();

    int group = lane >> 2, tg = lane & 3;
    int m0 = wid * 16;
    float acc[2][4];
#pragma unroll
    for (int nt = 0; nt < 2; nt++)
#pragma unroll
        for (int r = 0; r < 4; r++) acc[nt][r] = 0.f;

#pragma unroll
    for (int ks = 0; ks < 16; ks++) {
        int kb = ks * 8;
        uint32_t a[4];
        a[0] = As[(m0 + group)     * ZAS + kb + tg];
        a[1] = As[(m0 + group + 8) * ZAS + kb + tg];
        a[2] = As[(m0 + group)     * ZAS + kb + tg + 4];
        a[3] = As[(m0 + group + 8) * ZAS + kb + tg + 4];
        uint32_t b0[2], b1[2];
        b0[0] = Bs[(kb + tg)     * ZBS + group];
        b0[1] = Bs[(kb + tg + 4) * ZBS + group];
        b1[0] = Bs[(kb + tg)     * ZBS + 8 + group];
        b1[1] = Bs[(kb + tg + 4) * ZBS + 8 + group];
        mma8(acc[0], a, b0);
        mma8(acc[1], a, b1);
    }
    __syncthreads();

#pragma unroll
    for (int nt = 0; nt < 2; nt++)
#pragma unroll
        for (int half = 0; half < 2; half++) {
            int m  = m0 + group + half * 8;
            int h0 = nt * 8 + tg * 2;
            st[h0       * 129 + m] = acc[nt][half * 2 + 0];
            st[(h0 + 1) * 129 + m] = acc[nt][half * 2 + 1];
        }
    __syncthreads();

    int wwin = blk >> 5;
    int rembase = (blk & 31) * 128;
#pragma unroll
    for (int i = 0; i < 8; i++) {
        int idx = tid + 256 * i;
        int h = idx >> 7, m = idx & 127;
        out[((size_t)(wwin * 16 + h)) * 4096 + rembase + m] = st[h * 129 + m];
    }
}

// ---------------- local attention ----------------
#define ATTN_SMEM ((32 * 48 + 2 * 128 * 52) * 4)
__global__ __launch_bounds__(256) void attn_kernel(const float* __restrict__ q,
                                                   const float* __restrict__ k,
                                                   const float* __restrict__ v,
                                                   const float* __restrict__ bias,
                                                   float* __restrict__ o)
{
    extern __shared__ float sm[];
    float* qs = sm;
    float* ks = sm + 32 * 48;
    float* vs = ks + 128 * 52;
    int w = blockIdx.x, h = blockIdx.y;
    int tid = threadIdx.x;

    for (int i = tid; i < 32 * 48; i += 256) {
        int r = i / 48, c = i - r * 48;
        qs[i] = q[(size_t)(w * 32 + r) * CA + h * 48 + c];
    }
    for (int i = tid; i < 128 * 48; i += 256) {
        int r = i / 48, c = i - r * 48;
        int tok = w * 32 - 48 + r;
        tok = tok < 0 ? 0 : (tok > 4095 ? 4095 : tok);
        ks[r * 52 + c] = k[(size_t)tok * CA + h * 48 + c];
        vs[r * 52 + c] = v[(size_t)tok * CA + h * 48 + c];
    }
    __syncthreads();

    int qi = tid >> 3, g = tid & 7;
    float4 qreg[12];
#pragma unroll
    for (int j = 0; j < 12; j++) qreg[j] = *(const float4*)&qs[qi * 48 + 4 * j];

    const float scale = 0.14433756729740643f;
    float sc[16];
    const float* bp = bias + ((size_t)(w * 16 + h) * 32 + qi) * 128;
#pragma unroll
    for (int jj = 0; jj < 16; jj++) {
        int kj = g + 8 * jj;
        int tok = w * 32 - 48 + kj;
        if (tok < 0 || tok >= 4096) { sc[jj] = -1e9f; continue; }
        const float4* kp = (const float4*)&ks[kj * 52];
        float acc = 0.f;
#pragma unroll
        for (int j = 0; j < 12; j++) {
            float4 kv = kp[j];
            acc += qreg[j].x * kv.x + qreg[j].y * kv.y
                 + qreg[j].z * kv.z + qreg[j].w * kv.w;
        }
        sc[jj] = acc * scale + bp[kj];
    }
    float mx = sc[0];
#pragma unroll
    for (int jj = 1; jj < 16; jj++) mx = fmaxf(mx, sc[jj]);
#pragma unroll
    for (int o2 = 1; o2 < 8; o2 <<= 1) mx = fmaxf(mx, __shfl_xor_sync(0xffffffffu, mx, o2));
    float sum = 0.f;
#pragma unroll
    for (int jj = 0; jj < 16; jj++) { sc[jj] = expf(sc[jj] - mx); sum += sc[jj]; }
#pragma unroll
    for (int o2 = 1; o2 < 8; o2 <<= 1) sum += __shfl_xor_sync(0xffffffffu, sum, o2);
    float inv = 1.f / sum;

    float oa[48];
#pragma unroll
    for (int d = 0; d < 48; d++) oa[d] = 0.f;
#pragma unroll
    for (int jj = 0; jj < 16; jj++) {
        float p = sc[jj] * inv;
        const float4* vp = (const float4*)&vs[(g + 8 * jj) * 52];
#pragma unroll
        for (int j = 0; j < 12; j++) {
            float4 vv = vp[j];
            oa[4 * j + 0] += p * vv.x; oa[4 * j + 1] += p * vv.y;
            oa[4 * j + 2] += p * vv.z; oa[4 * j + 3] += p * vv.w;
        }
    }
#pragma unroll
    for (int o2 = 1; o2 < 8; o2 <<= 1)
#pragma unroll
        for (int d = 0; d < 48; d++)
            oa[d] += __shfl_xor_sync(0xffffffffu, oa[d], o2);
#pragma unroll
    for (int j = 0; j < 6; j++) {
        int d = g * 6 + j;
        o[(size_t)(w * 32 + qi) * CA + h * 48 + d] = oa[d];
    }
}

// ---------------- launch ----------------
extern "C" void kernel_launch(void* const* d_in, const int* in_sizes, int n_in,
                              void* d_out, int out_size)
{
    const float* a        = (const float*)d_in[0];
    const float* s        = (const float*)d_in[1];
    const float* z        = (const float*)d_in[2];
    const float* gamma_s  = (const float*)d_in[3];
    const float* ws       = (const float*)d_in[4];
    const float* bs       = (const float*)d_in[5];
    const float* wskip    = (const float*)d_in[6];
    const float* lnzg     = (const float*)d_in[7];
    const float* wz       = (const float*)d_in[8];
    const float* wq       = (const float*)d_in[9];
    const float* bq       = (const float*)d_in[10];
    const float* wk       = (const float*)d_in[11];
    const float* wv       = (const float*)d_in[12];
    const float* wg       = (const float*)d_in[13];
    const float* bg       = (const float*)d_in[14];
    const float* wo       = (const float*)d_in[15];
    const float* bo       = (const float*)d_in[16];
    const float* wlast    = (const float*)d_in[17];
    const float* blast    = (const float*)d_in[18];
    float* out = (float*)d_out;

    float *p_sln, *p_alnr, *p_aln, *p_t2, *p_q, *p_k, *p_v, *p_g, *p_o, *p_bias;
    cudaGetSymbolAddress((void**)&p_sln,  g_sln);
    cudaGetSymbolAddress((void**)&p_alnr, g_alnr);
    cudaGetSymbolAddress((void**)&p_aln,  g_aln);
    cudaGetSymbolAddress((void**)&p_t2,   g_t2);
    cudaGetSymbolAddress((void**)&p_q,    g_q);
    cudaGetSymbolAddress((void**)&p_k,    g_k);
    cudaGetSymbolAddress((void**)&p_v,    g_v);
    cudaGetSymbolAddress((void**)&p_g,    g_g);
    cudaGetSymbolAddress((void**)&p_o,    g_o);
    cudaGetSymbolAddress((void**)&p_bias, g_bias);

    cudaFuncSetAttribute(attn_kernel,  cudaFuncAttributeMaxDynamicSharedMemorySize, ATTN_SMEM);
    cudaFuncSetAttribute(bias2_kernel, cudaFuncAttributeMaxDynamicSharedMemorySize, BIAS2_SMEM);

    dim3 gg64(12, 32);   // BN=64 grids (adaln)
    dim3 gg128(6, 32);   // BN=128 grids

    ln_s_kernel<<<512, 256>>>(s, gamma_s, p_sln);                                    // 0
    ln_a_kernel<<<512, 256>>>(a, p_alnr);                                            // 1

    // aln = sigmoid(sln@ws + bs) * ln(a) + sln@wskip
    adaln_kernel<<<gg64, 256>>>(p_sln, ws, wskip, bs, p_alnr, p_aln);                // 2

    bias2_kernel<<<4096, 256, BIAS2_SMEM>>>(z, lnzg, wz, p_bias);                    // 3

    tgemm_qkvg<<<dim3(6, 32, 4), 256>>>(p_aln, wq, wk, wv, wg, bq, bg,
                                        p_q, p_k, p_v, p_g);                         // 4

    attn_kernel<<<dim3(128, 16), 256, ATTN_SMEM>>>(p_q, p_k, p_v, p_bias, p_o);      // 5

    // t2 = (g * o) @ wo + bo
    tgemm_k<<<gg128, 256>>>(p_o, p_g, wo, bo, nullptr, p_t2, 768, 0);                // 6
    // out = sigmoid(s @ wlast + blast) * t2
    tgemm_k<<<gg128, 256>>>(s, nullptr, wlast, blast, p_t2, out, 384, 1);            // 7
}